// round 14
// baseline (speedup 1.0000x reference)
#include <cuda_runtime.h>
#include <cuda_bf16.h>
#include <cstdint>

namespace {
constexpr int kB   = 16;
constexpr int kRows = kB * 512;  // 8192
}

// ---------------- scratch (device globals; no allocation) -------------------
__device__ __align__(16) __nv_bfloat16 g_wTt[2 * 256 * 256];   // wT^T bf16 [g][co2][i]
__device__ __align__(16) __nv_bfloat16 g_hp[kRows * 1024];     // pooled hidden bf16
__device__ __align__(16) __nv_bfloat16 g_scb[kRows * 512];     // scores bf16
__device__ __align__(16) __nv_bfloat16 g_at[kRows * 512];      // attn bf16
__device__ __align__(16) __nv_bfloat16 g_pat[512 * 1024];      // patterns bf16 [m][lp]

// ---------------- PTX helpers ------------------------------------------------
__device__ __forceinline__ void cp_async16(uint32_t dst, const void* src) {
  asm volatile("cp.async.cg.shared.global [%0], [%1], 16;\n" ::"r"(dst), "l"(src));
}
#define CP_COMMIT() asm volatile("cp.async.commit_group;\n" ::: "memory")
#define CP_WAIT(n) asm volatile("cp.async.wait_group %0;\n" ::"n"(n) : "memory")

__device__ __forceinline__ void ldsm_x4(uint32_t (&r)[4], uint32_t addr) {
  asm volatile(
      "ldmatrix.sync.aligned.m8n8.x4.shared.b16 {%0,%1,%2,%3}, [%4];"
      : "=r"(r[0]), "=r"(r[1]), "=r"(r[2]), "=r"(r[3])
      : "r"(addr));
}
__device__ __forceinline__ void ldsm_x4_t(uint32_t (&r)[4], uint32_t addr) {
  asm volatile(
      "ldmatrix.sync.aligned.m8n8.x4.trans.shared.b16 {%0,%1,%2,%3}, [%4];"
      : "=r"(r[0]), "=r"(r[1]), "=r"(r[2]), "=r"(r[3])
      : "r"(addr));
}

__device__ __forceinline__ void mma_16816(float (&c)[4], const uint32_t (&a)[4],
                                          const uint32_t b0, const uint32_t b1) {
  asm volatile(
      "mma.sync.aligned.m16n8k16.row.col.f32.bf16.bf16.f32 "
      "{%0,%1,%2,%3}, {%4,%5,%6,%7}, {%8,%9}, {%0,%1,%2,%3};"
      : "+f"(c[0]), "+f"(c[1]), "+f"(c[2]), "+f"(c[3])
      : "r"(a[0]), "r"(a[1]), "r"(a[2]), "r"(a[3]), "r"(b0), "r"(b1));
}

__device__ __forceinline__ uint32_t pack_bf16(float a, float b) {
  __nv_bfloat162 p = __floats2bfloat162_rn(a, b);
  return *(uint32_t*)&p;
}

__device__ __forceinline__ void cvt_store16(char* d, const float4 (&v)[4]) {
  uint4 q0, q1;
  q0.x = pack_bf16(v[0].x, v[0].y); q0.y = pack_bf16(v[0].z, v[0].w);
  q0.z = pack_bf16(v[1].x, v[1].y); q0.w = pack_bf16(v[1].z, v[1].w);
  q1.x = pack_bf16(v[2].x, v[2].y); q1.y = pack_bf16(v[2].z, v[2].w);
  q1.z = pack_bf16(v[3].x, v[3].y); q1.w = pack_bf16(v[3].z, v[3].w);
  *(uint4*)d = q0;
  *((uint4*)d + 1) = q1;
}

// ---------------------------------------------------------------------------
// k0: merged launch.
//   bid < 512   : patterns fp32 -> bf16 vec convert
//   512..543    : wT -> g_wTt tiled transpose
//   544..1567   : k1 (grouped 1x1 conv + bias + ReLU + maxpool2 -> g_hp bf16)
//                 w1 converted inline (A resident, K=128); r10 two-sync loop.
// dyn smem 52224: k1 A[128][272] resident | B 2x8704
// ---------------------------------------------------------------------------
__global__ __launch_bounds__(256) void k0_all(
    const float* __restrict__ x, const float* __restrict__ w1,
    const float* __restrict__ b1, const float* __restrict__ wT,
    const float* __restrict__ pat) {
  extern __shared__ __align__(16) char smem[];
  const int bid = blockIdx.x;
  const int t = threadIdx.x;

  if (bid < 512) {  // patterns: vec4 convert
    const int i2 = (bid * 256 + t) * 4;
    const float4 v = *(const float4*)(pat + i2);
    uint2 o;
    o.x = pack_bf16(v.x, v.y);
    o.y = pack_bf16(v.z, v.w);
    *(uint2*)&g_pat[i2] = o;
    return;
  }
  if (bid < 544) {  // wT transpose: 32 tiles of 64x64
    float* sm = (float*)smem;  // [64][68]
    const int tb = bid - 512;
    const int g = tb >> 4, ti = (tb >> 2) & 3, tc = tb & 3;
    const float* src = wT + ((size_t)(g * 256 + ti * 64)) * 256 + tc * 64;
#pragma unroll
    for (int k = 0; k < 4; ++k) {
      const int idx = t + k * 256;
      const int r = idx >> 4, c4 = (idx & 15) * 4;
      *(float4*)&sm[r * 68 + c4] = *(const float4*)(src + (size_t)r * 256 + c4);
    }
    __syncthreads();
    __nv_bfloat16* dst =
        g_wTt + (size_t)g * 65536 + (size_t)(tc * 64) * 256 + ti * 64;
#pragma unroll
    for (int k = 0; k < 4; ++k) {
      const int idx = t + k * 256;
      const int orow = idx >> 4, ocol = (idx & 15) * 4;
      uint2 o;
      o.x = pack_bf16(sm[(ocol + 0) * 68 + orow], sm[(ocol + 1) * 68 + orow]);
      o.y = pack_bf16(sm[(ocol + 2) * 68 + orow], sm[(ocol + 3) * 68 + orow]);
      *(uint2*)&dst[(size_t)orow * 256 + ocol] = o;
    }
    return;
  }

  // ------------------------- k1 body -------------------------
  const int kbid = bid - 544;
  const int w = t >> 5, lid = t & 31;
  const int wm = w >> 2, wn = w & 3;
  const int bx = kbid & 15, by = (kbid >> 4) & 1, bz = kbid >> 5;
  const int b = bz >> 1, g = bz & 1;
  const uint32_t sAb = (uint32_t)__cvta_generic_to_shared(smem);
  constexpr uint32_t BO = 34816;  // A resident: 128 rows x 272B

  // A: w1 slice [128 o][128 k] fp32 -> bf16 resident smem, pitch 272B
  const float* w1g = w1 + (size_t)(g * 256 + by * 128) * 128;
#pragma unroll
  for (int i = 0; i < 4; ++i) {
    const int idx = t + i * 256;
    const int row = idx >> 3, seg = idx & 7;
    const float4* p = (const float4*)(w1g + (size_t)row * 128 + seg * 16);
    const float4 va[4] = {p[0], p[1], p[2], p[3]};
    cvt_store16(smem + row * 272 + seg * 32, va);
  }

  // B: x fp32 LDG prefetch -> cvt -> smem [32 k][272B], 2 stages
  const float* xB = x + ((size_t)(b * 256 + g * 128)) * 2048 + bx * 128;
  const int brow = t >> 3, bcq = t & 7;
  const float* xrow = xB + (size_t)brow * 2048 + bcq * 16;
  float4 v[4];
  auto ldB = [&](int it) {
    const float4* p = (const float4*)(xrow + (size_t)it * 32 * 2048);
#pragma unroll
    for (int q = 0; q < 4; ++q) v[q] = p[q];
  };
  auto stB = [&](int s) {
    cvt_store16(smem + BO + s * 8704 + brow * 272 + bcq * 32, v);
  };

  float acc[4][4][4];
#pragma unroll
  for (int mt = 0; mt < 4; ++mt)
#pragma unroll
    for (int nt = 0; nt < 4; ++nt)
#pragma unroll
      for (int i = 0; i < 4; ++i) acc[mt][nt][i] = 0.f;

  ldB(0);
  const uint32_t aAddr0 = sAb + (wm * 64 + (lid & 15)) * 272 + (lid >> 4) * 16;
  const uint32_t bAddr0 = sAb + BO +
      (((lid >> 3) & 1) * 8 + (lid & 7)) * 272 + (wn * 32 + (lid >> 4) * 8) * 2;

#pragma unroll 1
  for (int it = 0; it < 4; ++it) {
    stB(it & 1);
    __syncthreads();
    if (it + 1 < 4) ldB(it + 1);
    const uint32_t sOB = (uint32_t)(it & 1) * 8704;
#pragma unroll
    for (int ks = 0; ks < 2; ++ks) {
      uint32_t afr[4][4];
      uint32_t bfr[4][2];
#pragma unroll
      for (int mt = 0; mt < 4; ++mt)
        ldsm_x4(afr[mt], aAddr0 + mt * 16 * 272 + it * 64 + ks * 32);
#pragma unroll
      for (int nt2 = 0; nt2 < 2; ++nt2) {
        uint32_t r4[4];
        ldsm_x4_t(r4, bAddr0 + sOB + ks * 16 * 272 + nt2 * 32);
        bfr[nt2 * 2 + 0][0] = r4[0]; bfr[nt2 * 2 + 0][1] = r4[1];
        bfr[nt2 * 2 + 1][0] = r4[2]; bfr[nt2 * 2 + 1][1] = r4[3];
      }
#pragma unroll
      for (int mt = 0; mt < 4; ++mt)
#pragma unroll
        for (int nt = 0; nt < 4; ++nt)
          mma_16816(acc[mt][nt], afr[mt], bfr[nt][0], bfr[nt][1]);
    }
    __syncthreads();
  }

  // epilogue: bias + relu + maxpool2 -> stage -> coalesced bf16 store
  __nv_bfloat16* sH = (__nv_bfloat16*)smem;  // [128][72]
#pragma unroll
  for (int mt = 0; mt < 4; ++mt) {
    const int m = wm * 64 + mt * 16 + (lid >> 2);
    const int og = g * 256 + by * 128 + m;
    const float bias0 = b1[og];
    const float bias1 = b1[og + 8];
#pragma unroll
    for (int nt = 0; nt < 4; ++nt) {
      const int np = wn * 16 + nt * 4 + (lid & 3);
      sH[m * 72 + np] =
          __float2bfloat16(fmaxf(fmaxf(acc[mt][nt][0], acc[mt][nt][1]) + bias0, 0.f));
      sH[(m + 8) * 72 + np] =
          __float2bfloat16(fmaxf(fmaxf(acc[mt][nt][2], acc[mt][nt][3]) + bias1, 0.f));
    }
  }
  __syncthreads();
  const size_t rowbase = (size_t)(b * 512 + g * 256 + by * 128);
  const int colbase = bx * 64;
#pragma unroll
  for (int p = 0; p < 4; ++p) {
    const int idx = t + p * 256;
    const int row = idx >> 3, ch = idx & 7;
    *(uint4*)&g_hp[(rowbase + row) * 1024 + colbase + ch * 8] =
        *(uint4*)&sH[row * 72 + ch * 8];
  }
}

// ---------------------------------------------------------------------------
// k2: scores = Hp @ P^T (K=1024) -> g_scb bf16  (validated r10)
// ---------------------------------------------------------------------------
__global__ __launch_bounds__(256, 2) void kgemm_scores() {
  constexpr int ITERS = 16;
  extern __shared__ __align__(16) char smem[];  // A 2x18432 | B 2x18432
  const int t = threadIdx.x, w = t >> 5, lid = t & 31;
  const int wm = w >> 2, wn = w & 3;
  const int n0 = blockIdx.x * 128;
  const int r0 = blockIdx.y * 128;
  const uint32_t sAb = (uint32_t)__cvta_generic_to_shared(smem);
  constexpr uint32_t BOFF = 36864;
  const char* Ab = (const char*)(g_hp + (size_t)r0 * 1024);
  const char* Bb = (const char*)(g_pat + (size_t)n0 * 1024);

  auto load_tile = [&](int s, int it) {
#pragma unroll
    for (int i = 0; i < 4; ++i) {
      const int idx = t + i * 256;
      const int row = idx >> 3, ch = idx & 7;
      const size_t go = (size_t)row * 2048 + it * 128 + ch * 16;
      const uint32_t so = (uint32_t)s * 18432 + row * 144 + ch * 16;
      cp_async16(sAb + so, Ab + go);
      cp_async16(sAb + BOFF + so, Bb + go);
    }
    CP_COMMIT();
  };

  float acc[4][4][4];
#pragma unroll
  for (int mt = 0; mt < 4; ++mt)
#pragma unroll
    for (int nt = 0; nt < 4; ++nt)
#pragma unroll
      for (int i = 0; i < 4; ++i) acc[mt][nt][i] = 0.f;

  load_tile(0, 0);
  const uint32_t aAddr0 = sAb + (wm * 64 + (lid & 15)) * 144 + (lid >> 4) * 16;
  const uint32_t bAddr0 = sAb + BOFF +
      (wn * 32 + ((lid >> 4) ? 8 : 0) + (lid & 7)) * 144 + ((lid >> 3) & 1) * 16;

#pragma unroll 1
  for (int it = 0; it < ITERS; ++it) {
    CP_WAIT(0);
    __syncthreads();
    if (it + 1 < ITERS) load_tile((it + 1) & 1, it + 1);
    const uint32_t sO = (uint32_t)(it & 1) * 18432;
#pragma unroll
    for (int ks = 0; ks < 4; ++ks) {
      uint32_t afr[4][4];
      uint32_t bfr[4][2];
#pragma unroll
      for (int mt = 0; mt < 4; ++mt)
        ldsm_x4(afr[mt], aAddr0 + sO + mt * 16 * 144 + ks * 32);
#pragma unroll
      for (int nt2 = 0; nt2 < 2; ++nt2) {
        uint32_t r4[4];
        ldsm_x4(r4, bAddr0 + sO + nt2 * 16 * 144 + ks * 32);
        bfr[nt2 * 2 + 0][0] = r4[0]; bfr[nt2 * 2 + 0][1] = r4[1];
        bfr[nt2 * 2 + 1][0] = r4[2]; bfr[nt2 * 2 + 1][1] = r4[3];
      }
#pragma unroll
      for (int mt = 0; mt < 4; ++mt)
#pragma unroll
        for (int nt = 0; nt < 4; ++nt)
          mma_16816(acc[mt][nt], afr[mt], bfr[nt][0], bfr[nt][1]);
    }
  }

  __nv_bfloat16* Crow = g_scb + (size_t)(r0 + wm * 64) * 512 + n0 + wn * 32;
  const int rr = lid >> 2;
  const int cc = (lid & 3) * 2;
#pragma unroll
  for (int mt = 0; mt < 4; ++mt)
#pragma unroll
    for (int nt = 0; nt < 4; ++nt) {
      *(uint32_t*)&Crow[(size_t)(mt * 16 + rr) * 512 + nt * 8 + cc] =
          pack_bf16(acc[mt][nt][0], acc[mt][nt][1]);
      *(uint32_t*)&Crow[(size_t)(mt * 16 + rr + 8) * 512 + nt * 8 + cc] =
          pack_bf16(acc[mt][nt][2], acc[mt][nt][3]);
    }
}

// ---------------------------------------------------------------------------
// k3: softmax over m=512 — warp per row, bf16 in/out, NO max pass
// (scores |s| <~ 2 << 80: exp cannot overflow in fp32)
// ---------------------------------------------------------------------------
__global__ __launch_bounds__(256) void k3_softmax() {
  const int wid = threadIdx.x >> 5, lane = threadIdx.x & 31;
  const size_t row = (size_t)blockIdx.x * 8 + wid;
  const uint4* rp = (const uint4*)(g_scb + row * 512);
  const uint4 q0 = rp[lane];
  const uint4 q1 = rp[lane + 32];

  float f[16];
  {
    const uint32_t us[8] = {q0.x, q0.y, q0.z, q0.w, q1.x, q1.y, q1.z, q1.w};
#pragma unroll
    for (int i = 0; i < 8; ++i) {
      const __nv_bfloat162 p = *(const __nv_bfloat162*)&us[i];
      f[2 * i] = __bfloat162float(p.x);
      f[2 * i + 1] = __bfloat162float(p.y);
    }
  }
  float s = 0.f;
#pragma unroll
  for (int i = 0; i < 16; ++i) {
    f[i] = __expf(f[i]);
    s += f[i];
  }
#pragma unroll
  for (int o = 16; o; o >>= 1) s += __shfl_xor_sync(0xffffffffu, s, o);
  const float inv = 1.f / s;

  uint4 o0, o1;
  o0.x = pack_bf16(f[0] * inv, f[1] * inv);
  o0.y = pack_bf16(f[2] * inv, f[3] * inv);
  o0.z = pack_bf16(f[4] * inv, f[5] * inv);
  o0.w = pack_bf16(f[6] * inv, f[7] * inv);
  o1.x = pack_bf16(f[8] * inv, f[9] * inv);
  o1.y = pack_bf16(f[10] * inv, f[11] * inv);
  o1.z = pack_bf16(f[12] * inv, f[13] * inv);
  o1.w = pack_bf16(f[14] * inv, f[15] * inv);
  uint4* op = (uint4*)(g_at + row * 512);
  op[lane] = o0;
  op[lane + 32] = o1;
}

// ---------------------------------------------------------------------------
// k45: FUSED retrieval + ConvT + bias + ReLU + residual  (validated r13)
// ---------------------------------------------------------------------------
__global__ __launch_bounds__(256, 2) void k45_fused(
    const float* __restrict__ x, const float* __restrict__ bT,
    const float* __restrict__ rzp, float* __restrict__ out) {
  extern __shared__ __align__(16) char smem[];
  const int t = threadIdx.x, w = t >> 5, lid = t & 31;
  const int wm = w >> 2, wn = w & 3;
  const int by = blockIdx.x, bz = blockIdx.y;
  const int b = bz >> 1, g = bz & 1;
  const int lp0 = by * 128;
  const uint32_t sAb = (uint32_t)__cvta_generic_to_shared(smem);
  constexpr uint32_t P1_BOFF = 20480;
  constexpr uint32_t HR = 37888;
  __nv_bfloat16* hrp = (__nv_bfloat16*)(smem + HR);

  const char* Bb1 = (const char*)(g_pat + lp0);

  // ---------------- Phase 1: two 128-c halves of hr ----------------
#pragma unroll 1
  for (int half = 0; half < 2; ++half) {
    const int r0 = b * 512 + g * 256 + half * 128;
    const char* Ab = (const char*)(g_at + (size_t)r0 * 512);

    auto load_tile = [&](int s, int it) {
#pragma unroll
      for (int i = 0; i < 2; ++i) {
        const int idx = t + i * 256;
        const int row = idx >> 2, ch = idx & 3;
        cp_async16(sAb + s * 10240 + row * 80 + ch * 16,
                   Ab + (size_t)row * 1024 + it * 64 + ch * 16);
      }
#pragma unroll
      for (int i = 0; i < 2; ++i) {
        const int idx = t + i * 256;
        const int row = idx >> 4, ch = idx & 15;
        cp_async16(sAb + P1_BOFF + s * 8704 + row * 272 + ch * 16,
                   Bb1 + (size_t)(it * 32 + row) * 2048 + ch * 16);
      }
      CP_COMMIT();
    };

    float acc[4][4][4];
#pragma unroll
    for (int mt = 0; mt < 4; ++mt)
#pragma unroll
      for (int nt = 0; nt < 4; ++nt)
#pragma unroll
        for (int i = 0; i < 4; ++i) acc[mt][nt][i] = 0.f;

    __syncthreads();
    load_tile(0, 0);
    const uint32_t aAddr0 = sAb + (wm * 64 + (lid & 15)) * 80 + (lid >> 4) * 16;
    const uint32_t bAddr0 = sAb + P1_BOFF +
        (((lid >> 3) & 1) * 8 + (lid & 7)) * 272 + (wn * 32 + (lid >> 4) * 8) * 2;

#pragma unroll 1
    for (int it = 0; it < 16; ++it) {
      CP_WAIT(0);
      __syncthreads();
      if (it + 1 < 16) load_tile((it + 1) & 1, it + 1);
      const uint32_t sOA = (uint32_t)(it & 1) * 10240;
      const uint32_t sOB = (uint32_t)(it & 1) * 8704;
#pragma unroll
      for (int ks = 0; ks < 2; ++ks) {
        uint32_t afr[4][4];
        uint32_t bfr[4][2];
#pragma unroll
        for (int mt = 0; mt < 4; ++mt)
          ldsm_x4(afr[mt], aAddr0 + sOA + mt * 16 * 80 + ks * 32);
#pragma unroll
        for (int nt2 = 0; nt2 < 2; ++nt2) {
          uint32_t r4[4];
          ldsm_x4_t(r4, bAddr0 + sOB + ks * 16 * 272 + nt2 * 32);
          bfr[nt2 * 2 + 0][0] = r4[0]; bfr[nt2 * 2 + 0][1] = r4[1];
          bfr[nt2 * 2 + 1][0] = r4[2]; bfr[nt2 * 2 + 1][1] = r4[3];
        }
#pragma unroll
        for (int mt = 0; mt < 4; ++mt)
#pragma unroll
          for (int nt = 0; nt < 4; ++nt)
            mma_16816(acc[mt][nt], afr[mt], bfr[nt][0], bfr[nt][1]);
      }
    }

    // store acc -> hr[c][lp] bf16
#pragma unroll
    for (int mt = 0; mt < 4; ++mt) {
      const int c = half * 128 + wm * 64 + mt * 16 + (lid >> 2);
#pragma unroll
      for (int nt = 0; nt < 4; ++nt) {
        const int lp = wn * 32 + nt * 8 + (lid & 3) * 2;
        *(uint32_t*)((char*)hrp + c * 272 + lp * 2) =
            pack_bf16(acc[mt][nt][0], acc[mt][nt][1]);
        *(uint32_t*)((char*)hrp + (c + 8) * 272 + lp * 2) =
            pack_bf16(acc[mt][nt][2], acc[mt][nt][3]);
      }
    }
  }
  __syncthreads();

  // ---------------- Phase 2: two 128-co2 halves of y ----------------
  const float rz = rzp[0];
  const uint32_t aAddr2 = sAb + (wm * 64 + (lid & 15)) * 144 + (lid >> 4) * 16;
  const uint32_t bAddr2 = sAb + HR +
      (((lid >> 3) & 1) * 8 + (lid & 7)) * 272 + (wn * 32 + (lid >> 4) * 8) * 2;

#pragma unroll 1
  for (int cb = 0; cb < 2; ++cb) {
    const char* Awt =
        (const char*)(g_wTt + (size_t)g * 65536 + (size_t)cb * 128 * 256);

    auto loadA2 = [&](int s, int it) {
#pragma unroll
      for (int i = 0; i < 4; ++i) {
        const int idx = t + i * 256;
        const int row = idx >> 3, ch = idx & 7;
        cp_async16(sAb + s * 18432 + row * 144 + ch * 16,
                   Awt + (size_t)row * 512 + it * 128 + ch * 16);
      }
      CP_COMMIT();
    };

    float acc[4][4][4];
#pragma unroll
    for (int mt = 0; mt < 4; ++mt)
#pragma unroll
      for (int nt = 0; nt < 4; ++nt)
#pragma unroll
        for (int i = 0; i < 4; ++i) acc[mt][nt][i] = 0.f;

    loadA2(0, 0);

#pragma unroll 1
    for (int it = 0; it < 4; ++it) {
      CP_WAIT(0);
      __syncthreads();
      if (it + 1 < 4) loadA2((it + 1) & 1, it + 1);
      const uint32_t sOA = (uint32_t)(it & 1) * 18432;
      const uint32_t bIt = (uint32_t)(it * 64) * 272;
#pragma unroll
      for (int ks = 0; ks < 4; ++ks) {
        uint32_t afr[4][4];
        uint32_t bfr[4][2];
#pragma unroll
        for (int mt = 0; mt < 4; ++mt)
          ldsm_x4(afr[mt], aAddr2 + sOA + mt * 16 * 144 + ks * 32);
#pragma unroll
        for (int nt2 = 0; nt2 < 2; ++nt2) {
          uint32_t r4[4];
          ldsm_x4_t(r4, bAddr2 + bIt + ks * 16 * 272 + nt2 * 32);
          bfr[nt2 * 2 + 0][0] = r4[0]; bfr[nt2 * 2 + 0][1] = r4[1];
          bfr[nt2 * 2 + 1][0] = r4[2]; bfr[nt2 * 2 + 1][1] = r4[3];
        }
#pragma unroll
        for (int mt = 0; mt < 4; ++mt)
#pragma unroll
          for (int nt = 0; nt < 4; ++nt)
            mma_16816(acc[mt][nt], afr[mt], bfr[nt][0], bfr[nt][1]);
      }
    }
    __syncthreads();

    // stage raw y (pre-bias) into sY[co 64][l 264] bf16
    __nv_bfloat16* sY = (__nv_bfloat16*)smem;
#pragma unroll
    for (int mt = 0; mt < 4; ++mt) {
      const int r1 = wm * 64 + mt * 16 + (lid >> 2);
      const int r2 = r1 + 8;
#pragma unroll
      for (int nt = 0; nt < 4; ++nt) {
        const int lp = wn * 32 + nt * 8 + (lid & 3) * 2;
        sY[(r1 >> 1) * 264 + 2 * lp + (r1 & 1)] = __float2bfloat16(acc[mt][nt][0]);
        sY[(r1 >> 1) * 264 + 2 * (lp + 1) + (r1 & 1)] = __float2bfloat16(acc[mt][nt][1]);
        sY[(r2 >> 1) * 264 + 2 * lp + (r2 & 1)] = __float2bfloat16(acc[mt][nt][2]);
        sY[(r2 >> 1) * 264 + 2 * (lp + 1) + (r2 & 1)] = __float2bfloat16(acc[mt][nt][3]);
      }
    }
    __syncthreads();

    // residual write: bias + relu + x + rz*y
    const int co_r = t >> 2;
    const int colb = (t & 3) * 4;
    const int cog = g * 128 + cb * 64 + co_r;
    const float bias = bT[cog];
    const size_t rowoff = ((size_t)b * 256 + cog) * 2048 + by * 256;
#pragma unroll
    for (int j = 0; j < 16; ++j) {
      const int col = colb + j * 16;
      const uint32_t* yp = (const uint32_t*)&sY[co_r * 264 + col];
      __nv_bfloat162 y0 = *(const __nv_bfloat162*)&yp[0];
      __nv_bfloat162 y1 = *(const __nv_bfloat162*)&yp[1];
      const float4 xv = *(const float4*)(x + rowoff + col);
      float4 o4;
      o4.x = xv.x + rz * fmaxf(__bfloat162float(y0.x) + bias, 0.f);
      o4.y = xv.y + rz * fmaxf(__bfloat162float(y0.y) + bias, 0.f);
      o4.z = xv.z + rz * fmaxf(__bfloat162float(y1.x) + bias, 0.f);
      o4.w = xv.w + rz * fmaxf(__bfloat162float(y1.y) + bias, 0.f);
      *(float4*)(out + rowoff + col) = o4;
    }
    __syncthreads();
  }
}

// ---------------------------------------------------------------------------
extern "C" void kernel_launch(void* const* d_in, const int* in_sizes, int n_in,
                              void* d_out, int out_size) {
  (void)in_sizes; (void)n_in; (void)out_size;
  const float* x        = (const float*)d_in[0];
  const float* w1       = (const float*)d_in[1];
  const float* b1       = (const float*)d_in[2];
  const float* patterns = (const float*)d_in[3];
  const float* wT       = (const float*)d_in[4];
  const float* bT       = (const float*)d_in[5];
  const float* RZ       = (const float*)d_in[6];
  float* out            = (float*)d_out;

  cudaFuncSetAttribute(k0_all,
                       cudaFuncAttributeMaxDynamicSharedMemorySize, 52224);
  cudaFuncSetAttribute(kgemm_scores,
                       cudaFuncAttributeMaxDynamicSharedMemorySize, 73728);
  cudaFuncSetAttribute(k45_fused,
                       cudaFuncAttributeMaxDynamicSharedMemorySize, 107520);

  k0_all<<<1568, 256, 52224>>>(x, w1, b1, wT, patterns);
  kgemm_scores<<<dim3(4, 64), 256, 73728>>>();
  k3_softmax<<<kRows / 8, 256>>>();
  k45_fused<<<dim3(8, 32), 256, 107520>>>(x, bT, RZ, out);
}

// round 15
// speedup vs baseline: 1.0349x; 1.0349x over previous
#include <cuda_runtime.h>
#include <cuda_bf16.h>
#include <cstdint>

namespace {
constexpr int kB   = 16;
constexpr int kRows = kB * 512;  // 8192
}

// ---------------- scratch (device globals; no allocation) -------------------
__device__ __align__(16) __nv_bfloat16 g_w1b[512 * 128];       // w1 bf16
__device__ __align__(16) __nv_bfloat16 g_wTt[2 * 256 * 256];   // wT^T bf16 [g][co2][i]
__device__ __align__(16) __nv_bfloat16 g_hp[kRows * 1024];     // pooled hidden bf16
__device__ __align__(16) __nv_bfloat16 g_scb[kRows * 512];     // scores bf16
__device__ __align__(16) __nv_bfloat16 g_at[kRows * 512];      // attn bf16
__device__ __align__(16) __nv_bfloat16 g_pat[512 * 1024];      // patterns bf16 [m][lp]

// ---------------- PTX helpers ------------------------------------------------
__device__ __forceinline__ void cp_async16(uint32_t dst, const void* src) {
  asm volatile("cp.async.cg.shared.global [%0], [%1], 16;\n" ::"r"(dst), "l"(src));
}
#define CP_COMMIT() asm volatile("cp.async.commit_group;\n" ::: "memory")
#define CP_WAIT(n) asm volatile("cp.async.wait_group %0;\n" ::"n"(n) : "memory")

__device__ __forceinline__ void ldsm_x4(uint32_t (&r)[4], uint32_t addr) {
  asm volatile(
      "ldmatrix.sync.aligned.m8n8.x4.shared.b16 {%0,%1,%2,%3}, [%4];"
      : "=r"(r[0]), "=r"(r[1]), "=r"(r[2]), "=r"(r[3])
      : "r"(addr));
}
__device__ __forceinline__ void ldsm_x4_t(uint32_t (&r)[4], uint32_t addr) {
  asm volatile(
      "ldmatrix.sync.aligned.m8n8.x4.trans.shared.b16 {%0,%1,%2,%3}, [%4];"
      : "=r"(r[0]), "=r"(r[1]), "=r"(r[2]), "=r"(r[3])
      : "r"(addr));
}

__device__ __forceinline__ void mma_16816(float (&c)[4], const uint32_t (&a)[4],
                                          const uint32_t b0, const uint32_t b1) {
  asm volatile(
      "mma.sync.aligned.m16n8k16.row.col.f32.bf16.bf16.f32 "
      "{%0,%1,%2,%3}, {%4,%5,%6,%7}, {%8,%9}, {%0,%1,%2,%3};"
      : "+f"(c[0]), "+f"(c[1]), "+f"(c[2]), "+f"(c[3])
      : "r"(a[0]), "r"(a[1]), "r"(a[2]), "r"(a[3]), "r"(b0), "r"(b1));
}

__device__ __forceinline__ uint32_t pack_bf16(float a, float b) {
  __nv_bfloat162 p = __floats2bfloat162_rn(a, b);
  return *(uint32_t*)&p;
}

__device__ __forceinline__ void cvt_store16(char* d, const float4 (&v)[4]) {
  uint4 q0, q1;
  q0.x = pack_bf16(v[0].x, v[0].y); q0.y = pack_bf16(v[0].z, v[0].w);
  q0.z = pack_bf16(v[1].x, v[1].y); q0.w = pack_bf16(v[1].z, v[1].w);
  q1.x = pack_bf16(v[2].x, v[2].y); q1.y = pack_bf16(v[2].z, v[2].w);
  q1.z = pack_bf16(v[3].x, v[3].y); q1.w = pack_bf16(v[3].z, v[3].w);
  *(uint4*)d = q0;
  *((uint4*)d + 1) = q1;
}

// ---------------------------------------------------------------------------
// Prep: w1 -> g_w1b, pat -> g_pat (vec cvt); wT -> g_wTt via tiled transpose.
// ---------------------------------------------------------------------------
__global__ __launch_bounds__(256) void kprep_all(const float* __restrict__ w1,
                                                 const float* __restrict__ wT,
                                                 const float* __restrict__ pat) {
  __shared__ __align__(16) float sm[64 * 68];
  const int bid = blockIdx.x;
  const int t = threadIdx.x;
  if (bid < 64) {
    const int idx = (bid * 256 + t) * 4;
    const float4 v = *(const float4*)(w1 + idx);
    uint2 o;
    o.x = pack_bf16(v.x, v.y);
    o.y = pack_bf16(v.z, v.w);
    *(uint2*)&g_w1b[idx] = o;
  } else if (bid < 576) {
    const int i2 = ((bid - 64) * 256 + t) * 4;
    const float4 v = *(const float4*)(pat + i2);
    uint2 o;
    o.x = pack_bf16(v.x, v.y);
    o.y = pack_bf16(v.z, v.w);
    *(uint2*)&g_pat[i2] = o;
  } else {
    const int tb = bid - 576;
    const int g = tb >> 4, ti = (tb >> 2) & 3, tc = tb & 3;
    const float* src = wT + ((size_t)(g * 256 + ti * 64)) * 256 + tc * 64;
#pragma unroll
    for (int k = 0; k < 4; ++k) {
      const int idx = t + k * 256;
      const int r = idx >> 4, c4 = (idx & 15) * 4;
      *(float4*)&sm[r * 68 + c4] = *(const float4*)(src + (size_t)r * 256 + c4);
    }
    __syncthreads();
    __nv_bfloat16* dst = g_wTt + (size_t)g * 65536 + (size_t)(tc * 64) * 256 + ti * 64;
#pragma unroll
    for (int k = 0; k < 4; ++k) {
      const int idx = t + k * 256;
      const int orow = idx >> 4, ocol = (idx & 15) * 4;
      uint2 o;
      o.x = pack_bf16(sm[(ocol + 0) * 68 + orow], sm[(ocol + 1) * 68 + orow]);
      o.y = pack_bf16(sm[(ocol + 2) * 68 + orow], sm[(ocol + 3) * 68 + orow]);
      *(uint2*)&dst[(size_t)orow * 256 + ocol] = o;
    }
  }
}

// ---------------------------------------------------------------------------
// k1: HMMA grouped 1x1 conv + bias + ReLU + maxpool2 -> g_hp bf16 (validated)
// ---------------------------------------------------------------------------
__global__ __launch_bounds__(256) void k1_hmma(const float* __restrict__ x,
                                               const float* __restrict__ b1) {
  __shared__ __align__(16) char smem[37888];
  const int t = threadIdx.x, w = t >> 5, lid = t & 31;
  const int wm = w >> 2, wn = w & 3;
  const int bx = blockIdx.x, by = blockIdx.y, bz = blockIdx.z;
  const int b = bz >> 1, g = bz & 1;
  const uint32_t sAb = (uint32_t)__cvta_generic_to_shared(smem);
  const char* Ag = (const char*)(g_w1b + (size_t)(g * 256 + by * 128) * 128);
  const float* xB = x + ((size_t)(b * 256 + g * 128)) * 2048 + bx * 128;

  const int brow = t >> 3, bcq = t & 7;
  const float* xrow = xB + (size_t)brow * 2048 + bcq * 16;

  auto ldA = [&](int s, int it) {
#pragma unroll
    for (int i = 0; i < 2; ++i) {
      const int idx = t + i * 256;
      const int row = idx >> 2, ch = idx & 3;
      cp_async16(sAb + s * 10240 + row * 80 + ch * 16,
                 Ag + row * 256 + it * 64 + ch * 16);
    }
    CP_COMMIT();
  };

  float4 v[4];
  auto ldB = [&](int it) {
    const float4* p = (const float4*)(xrow + (size_t)it * 32 * 2048);
#pragma unroll
    for (int q = 0; q < 4; ++q) v[q] = p[q];
  };
  auto stB = [&](int s) {
    cvt_store16(smem + 20480 + s * 8704 + brow * 272 + bcq * 32, v);
  };

  float acc[4][4][4];
#pragma unroll
  for (int mt = 0; mt < 4; ++mt)
#pragma unroll
    for (int nt = 0; nt < 4; ++nt)
#pragma unroll
      for (int i = 0; i < 4; ++i) acc[mt][nt][i] = 0.f;

  ldA(0, 0);
  ldB(0);
  const uint32_t aAddr0 = sAb + (wm * 64 + (lid & 15)) * 80 + (lid >> 4) * 16;
  const uint32_t bAddr0 = sAb + 20480 +
      (((lid >> 3) & 1) * 8 + (lid & 7)) * 272 + (wn * 32 + (lid >> 4) * 8) * 2;

#pragma unroll 1
  for (int it = 0; it < 4; ++it) {
    if (it + 1 < 4) {
      ldA((it + 1) & 1, it + 1);
      CP_WAIT(1);
    } else {
      CP_WAIT(0);
    }
    stB(it & 1);
    __syncthreads();
    if (it + 1 < 4) ldB(it + 1);
    const uint32_t sOA = (uint32_t)(it & 1) * 10240;
    const uint32_t sOB = (uint32_t)(it & 1) * 8704;
#pragma unroll
    for (int ks = 0; ks < 2; ++ks) {
      uint32_t afr[4][4];
      uint32_t bfr[4][2];
#pragma unroll
      for (int mt = 0; mt < 4; ++mt)
        ldsm_x4(afr[mt], aAddr0 + sOA + mt * 16 * 80 + ks * 32);
#pragma unroll
      for (int nt2 = 0; nt2 < 2; ++nt2) {
        uint32_t r4[4];
        ldsm_x4_t(r4, bAddr0 + sOB + ks * 16 * 272 + nt2 * 32);
        bfr[nt2 * 2 + 0][0] = r4[0]; bfr[nt2 * 2 + 0][1] = r4[1];
        bfr[nt2 * 2 + 1][0] = r4[2]; bfr[nt2 * 2 + 1][1] = r4[3];
      }
#pragma unroll
      for (int mt = 0; mt < 4; ++mt)
#pragma unroll
        for (int nt = 0; nt < 4; ++nt)
          mma_16816(acc[mt][nt], afr[mt], bfr[nt][0], bfr[nt][1]);
    }
    __syncthreads();
  }

  __nv_bfloat16* sH = (__nv_bfloat16*)smem;  // [128][72]
#pragma unroll
  for (int mt = 0; mt < 4; ++mt) {
    const int m = wm * 64 + mt * 16 + (lid >> 2);
    const int og = g * 256 + by * 128 + m;
    const float bias0 = b1[og];
    const float bias1 = b1[og + 8];
#pragma unroll
    for (int nt = 0; nt < 4; ++nt) {
      const int np = wn * 16 + nt * 4 + (lid & 3);
      sH[m * 72 + np] =
          __float2bfloat16(fmaxf(fmaxf(acc[mt][nt][0], acc[mt][nt][1]) + bias0, 0.f));
      sH[(m + 8) * 72 + np] =
          __float2bfloat16(fmaxf(fmaxf(acc[mt][nt][2], acc[mt][nt][3]) + bias1, 0.f));
    }
  }
  __syncthreads();
  const size_t rowbase = (size_t)(b * 512 + g * 256 + by * 128);
  const int colbase = bx * 64;
#pragma unroll
  for (int p = 0; p < 4; ++p) {
    const int idx = t + p * 256;
    const int row = idx >> 3, ch = idx & 7;
    *(uint4*)&g_hp[(rowbase + row) * 1024 + colbase + ch * 8] =
        *(uint4*)&sH[row * 72 + ch * 8];
  }
}

// ---------------------------------------------------------------------------
// k2: scores = Hp @ P^T (K=1024) -> g_scb bf16  (round-10, validated)
// ---------------------------------------------------------------------------
__global__ __launch_bounds__(256, 2) void kgemm_scores() {
  constexpr int ITERS = 16;
  extern __shared__ __align__(16) char smem[];  // A 2x18432 | B 2x18432
  const int t = threadIdx.x, w = t >> 5, lid = t & 31;
  const int wm = w >> 2, wn = w & 3;
  const int n0 = blockIdx.x * 128;
  const int r0 = blockIdx.y * 128;
  const uint32_t sAb = (uint32_t)__cvta_generic_to_shared(smem);
  constexpr uint32_t BOFF = 36864;
  const char* Ab = (const char*)(g_hp + (size_t)r0 * 1024);
  const char* Bb = (const char*)(g_pat + (size_t)n0 * 1024);

  auto load_tile = [&](int s, int it) {
#pragma unroll
    for (int i = 0; i < 4; ++i) {
      const int idx = t + i * 256;
      const int row = idx >> 3, ch = idx & 7;
      const size_t go = (size_t)row * 2048 + it * 128 + ch * 16;
      const uint32_t so = (uint32_t)s * 18432 + row * 144 + ch * 16;
      cp_async16(sAb + so, Ab + go);
      cp_async16(sAb + BOFF + so, Bb + go);
    }
    CP_COMMIT();
  };

  float acc[4][4][4];
#pragma unroll
  for (int mt = 0; mt < 4; ++mt)
#pragma unroll
    for (int nt = 0; nt < 4; ++nt)
#pragma unroll
      for (int i = 0; i < 4; ++i) acc[mt][nt][i] = 0.f;

  load_tile(0, 0);
  const uint32_t aAddr0 = sAb + (wm * 64 + (lid & 15)) * 144 + (lid >> 4) * 16;
  const uint32_t bAddr0 = sAb + BOFF +
      (wn * 32 + ((lid >> 4) ? 8 : 0) + (lid & 7)) * 144 + ((lid >> 3) & 1) * 16;

#pragma unroll 1
  for (int it = 0; it < ITERS; ++it) {
    CP_WAIT(0);
    __syncthreads();
    if (it + 1 < ITERS) load_tile((it + 1) & 1, it + 1);
    const uint32_t sO = (uint32_t)(it & 1) * 18432;
#pragma unroll
    for (int ks = 0; ks < 4; ++ks) {
      uint32_t afr[4][4];
      uint32_t bfr[4][2];
#pragma unroll
      for (int mt = 0; mt < 4; ++mt)
        ldsm_x4(afr[mt], aAddr0 + sO + mt * 16 * 144 + ks * 32);
#pragma unroll
      for (int nt2 = 0; nt2 < 2; ++nt2) {
        uint32_t r4[4];
        ldsm_x4(r4, bAddr0 + sO + nt2 * 16 * 144 + ks * 32);
        bfr[nt2 * 2 + 0][0] = r4[0]; bfr[nt2 * 2 + 0][1] = r4[1];
        bfr[nt2 * 2 + 1][0] = r4[2]; bfr[nt2 * 2 + 1][1] = r4[3];
      }
#pragma unroll
      for (int mt = 0; mt < 4; ++mt)
#pragma unroll
        for (int nt = 0; nt < 4; ++nt)
          mma_16816(acc[mt][nt], afr[mt], bfr[nt][0], bfr[nt][1]);
    }
  }

  __nv_bfloat16* Crow = g_scb + (size_t)(r0 + wm * 64) * 512 + n0 + wn * 32;
  const int rr = lid >> 2;
  const int cc = (lid & 3) * 2;
#pragma unroll
  for (int mt = 0; mt < 4; ++mt)
#pragma unroll
    for (int nt = 0; nt < 4; ++nt) {
      *(uint32_t*)&Crow[(size_t)(mt * 16 + rr) * 512 + nt * 8 + cc] =
          pack_bf16(acc[mt][nt][0], acc[mt][nt][1]);
      *(uint32_t*)&Crow[(size_t)(mt * 16 + rr + 8) * 512 + nt * 8 + cc] =
          pack_bf16(acc[mt][nt][2], acc[mt][nt][3]);
    }
}

// ---------------------------------------------------------------------------
// k3: softmax over m=512 — warp per row, bf16 in/out, NO max pass
// (scores |s| <~ 3 << 88: fp32 exp cannot overflow; mathematically identical)
// ---------------------------------------------------------------------------
__global__ __launch_bounds__(256) void k3_softmax() {
  const int wid = threadIdx.x >> 5, lane = threadIdx.x & 31;
  const size_t row = (size_t)blockIdx.x * 8 + wid;
  const uint4* rp = (const uint4*)(g_scb + row * 512);
  const uint4 q0 = rp[lane];
  const uint4 q1 = rp[lane + 32];

  float f[16];
  {
    const uint32_t us[8] = {q0.x, q0.y, q0.z, q0.w, q1.x, q1.y, q1.z, q1.w};
#pragma unroll
    for (int i = 0; i < 8; ++i) {
      const __nv_bfloat162 p = *(const __nv_bfloat162*)&us[i];
      f[2 * i] = __bfloat162float(p.x);
      f[2 * i + 1] = __bfloat162float(p.y);
    }
  }
  float s = 0.f;
#pragma unroll
  for (int i = 0; i < 16; ++i) {
    f[i] = __expf(f[i]);
    s += f[i];
  }
#pragma unroll
  for (int o = 16; o; o >>= 1) s += __shfl_xor_sync(0xffffffffu, s, o);
  const float inv = 1.f / s;

  uint4 o0, o1;
  o0.x = pack_bf16(f[0] * inv, f[1] * inv);
  o0.y = pack_bf16(f[2] * inv, f[3] * inv);
  o0.z = pack_bf16(f[4] * inv, f[5] * inv);
  o0.w = pack_bf16(f[6] * inv, f[7] * inv);
  o1.x = pack_bf16(f[8] * inv, f[9] * inv);
  o1.y = pack_bf16(f[10] * inv, f[11] * inv);
  o1.z = pack_bf16(f[12] * inv, f[13] * inv);
  o1.w = pack_bf16(f[14] * inv, f[15] * inv);
  uint4* op = (uint4*)(g_at + row * 512);
  op[lane] = o0;
  op[lane + 32] = o1;
}

// ---------------------------------------------------------------------------
// k45: FUSED retrieval + ConvT + bias + ReLU + residual  (validated r13)
// ---------------------------------------------------------------------------
__global__ __launch_bounds__(256, 2) void k45_fused(
    const float* __restrict__ x, const float* __restrict__ bT,
    const float* __restrict__ rzp, float* __restrict__ out) {
  extern __shared__ __align__(16) char smem[];
  const int t = threadIdx.x, w = t >> 5, lid = t & 31;
  const int wm = w >> 2, wn = w & 3;
  const int by = blockIdx.x, bz = blockIdx.y;
  const int b = bz >> 1, g = bz & 1;
  const int lp0 = by * 128;
  const uint32_t sAb = (uint32_t)__cvta_generic_to_shared(smem);
  constexpr uint32_t P1_BOFF = 20480;
  constexpr uint32_t HR = 37888;
  __nv_bfloat16* hrp = (__nv_bfloat16*)(smem + HR);

  const char* Bb1 = (const char*)(g_pat + lp0);

  // ---------------- Phase 1: two 128-c halves of hr ----------------
#pragma unroll 1
  for (int half = 0; half < 2; ++half) {
    const int r0 = b * 512 + g * 256 + half * 128;
    const char* Ab = (const char*)(g_at + (size_t)r0 * 512);

    auto load_tile = [&](int s, int it) {
#pragma unroll
      for (int i = 0; i < 2; ++i) {
        const int idx = t + i * 256;
        const int row = idx >> 2, ch = idx & 3;
        cp_async16(sAb + s * 10240 + row * 80 + ch * 16,
                   Ab + (size_t)row * 1024 + it * 64 + ch * 16);
      }
#pragma unroll
      for (int i = 0; i < 2; ++i) {
        const int idx = t + i * 256;
        const int row = idx >> 4, ch = idx & 15;
        cp_async16(sAb + P1_BOFF + s * 8704 + row * 272 + ch * 16,
                   Bb1 + (size_t)(it * 32 + row) * 2048 + ch * 16);
      }
      CP_COMMIT();
    };

    float acc[4][4][4];
#pragma unroll
    for (int mt = 0; mt < 4; ++mt)
#pragma unroll
      for (int nt = 0; nt < 4; ++nt)
#pragma unroll
        for (int i = 0; i < 4; ++i) acc[mt][nt][i] = 0.f;

    __syncthreads();
    load_tile(0, 0);
    const uint32_t aAddr0 = sAb + (wm * 64 + (lid & 15)) * 80 + (lid >> 4) * 16;
    const uint32_t bAddr0 = sAb + P1_BOFF +
        (((lid >> 3) & 1) * 8 + (lid & 7)) * 272 + (wn * 32 + (lid >> 4) * 8) * 2;

#pragma unroll 1
    for (int it = 0; it < 16; ++it) {
      CP_WAIT(0);
      __syncthreads();
      if (it + 1 < 16) load_tile((it + 1) & 1, it + 1);
      const uint32_t sOA = (uint32_t)(it & 1) * 10240;
      const uint32_t sOB = (uint32_t)(it & 1) * 8704;
#pragma unroll
      for (int ks = 0; ks < 2; ++ks) {
        uint32_t afr[4][4];
        uint32_t bfr[4][2];
#pragma unroll
        for (int mt = 0; mt < 4; ++mt)
          ldsm_x4(afr[mt], aAddr0 + sOA + mt * 16 * 80 + ks * 32);
#pragma unroll
        for (int nt2 = 0; nt2 < 2; ++nt2) {
          uint32_t r4[4];
          ldsm_x4_t(r4, bAddr0 + sOB + ks * 16 * 272 + nt2 * 32);
          bfr[nt2 * 2 + 0][0] = r4[0]; bfr[nt2 * 2 + 0][1] = r4[1];
          bfr[nt2 * 2 + 1][0] = r4[2]; bfr[nt2 * 2 + 1][1] = r4[3];
        }
#pragma unroll
        for (int mt = 0; mt < 4; ++mt)
#pragma unroll
          for (int nt = 0; nt < 4; ++nt)
            mma_16816(acc[mt][nt], afr[mt], bfr[nt][0], bfr[nt][1]);
      }
    }

    // store acc -> hr[c][lp] bf16 (rows = c, no transpose)
#pragma unroll
    for (int mt = 0; mt < 4; ++mt) {
      const int c = half * 128 + wm * 64 + mt * 16 + (lid >> 2);
#pragma unroll
      for (int nt = 0; nt < 4; ++nt) {
        const int lp = wn * 32 + nt * 8 + (lid & 3) * 2;
        *(uint32_t*)((char*)hrp + c * 272 + lp * 2) =
            pack_bf16(acc[mt][nt][0], acc[mt][nt][1]);
        *(uint32_t*)((char*)hrp + (c + 8) * 272 + lp * 2) =
            pack_bf16(acc[mt][nt][2], acc[mt][nt][3]);
      }
    }
  }
  __syncthreads();

  // ---------------- Phase 2: two 128-co2 halves of y ----------------
  const float rz = rzp[0];
  const uint32_t aAddr2 = sAb + (wm * 64 + (lid & 15)) * 144 + (lid >> 4) * 16;
  const uint32_t bAddr2 = sAb + HR +
      (((lid >> 3) & 1) * 8 + (lid & 7)) * 272 + (wn * 32 + (lid >> 4) * 8) * 2;

#pragma unroll 1
  for (int cb = 0; cb < 2; ++cb) {
    const char* Awt =
        (const char*)(g_wTt + (size_t)g * 65536 + (size_t)cb * 128 * 256);

    auto loadA2 = [&](int s, int it) {
#pragma unroll
      for (int i = 0; i < 4; ++i) {
        const int idx = t + i * 256;
        const int row = idx >> 3, ch = idx & 7;
        cp_async16(sAb + s * 18432 + row * 144 + ch * 16,
                   Awt + (size_t)row * 512 + it * 128 + ch * 16);
      }
      CP_COMMIT();
    };

    float acc[4][4][4];
#pragma unroll
    for (int mt = 0; mt < 4; ++mt)
#pragma unroll
      for (int nt = 0; nt < 4; ++nt)
#pragma unroll
        for (int i = 0; i < 4; ++i) acc[mt][nt][i] = 0.f;

    loadA2(0, 0);

#pragma unroll 1
    for (int it = 0; it < 4; ++it) {
      CP_WAIT(0);
      __syncthreads();
      if (it + 1 < 4) loadA2((it + 1) & 1, it + 1);
      const uint32_t sOA = (uint32_t)(it & 1) * 18432;
      const uint32_t bIt = (uint32_t)(it * 64) * 272;
#pragma unroll
      for (int ks = 0; ks < 4; ++ks) {
        uint32_t afr[4][4];
        uint32_t bfr[4][2];
#pragma unroll
        for (int mt = 0; mt < 4; ++mt)
          ldsm_x4(afr[mt], aAddr2 + sOA + mt * 16 * 144 + ks * 32);
#pragma unroll
        for (int nt2 = 0; nt2 < 2; ++nt2) {
          uint32_t r4[4];
          ldsm_x4_t(r4, bAddr2 + bIt + ks * 16 * 272 + nt2 * 32);
          bfr[nt2 * 2 + 0][0] = r4[0]; bfr[nt2 * 2 + 0][1] = r4[1];
          bfr[nt2 * 2 + 1][0] = r4[2]; bfr[nt2 * 2 + 1][1] = r4[3];
        }
#pragma unroll
        for (int mt = 0; mt < 4; ++mt)
#pragma unroll
          for (int nt = 0; nt < 4; ++nt)
            mma_16816(acc[mt][nt], afr[mt], bfr[nt][0], bfr[nt][1]);
      }
    }
    __syncthreads();  // A-stage reads done -> safe to reuse as sY

    // stage raw y (pre-bias) into sY[co 64][l 264] bf16
    __nv_bfloat16* sY = (__nv_bfloat16*)smem;
#pragma unroll
    for (int mt = 0; mt < 4; ++mt) {
      const int r1 = wm * 64 + mt * 16 + (lid >> 2);
      const int r2 = r1 + 8;
#pragma unroll
      for (int nt = 0; nt < 4; ++nt) {
        const int lp = wn * 32 + nt * 8 + (lid & 3) * 2;
        sY[(r1 >> 1) * 264 + 2 * lp + (r1 & 1)] = __float2bfloat16(acc[mt][nt][0]);
        sY[(r1 >> 1) * 264 + 2 * (lp + 1) + (r1 & 1)] = __float2bfloat16(acc[mt][nt][1]);
        sY[(r2 >> 1) * 264 + 2 * lp + (r2 & 1)] = __float2bfloat16(acc[mt][nt][2]);
        sY[(r2 >> 1) * 264 + 2 * (lp + 1) + (r2 & 1)] = __float2bfloat16(acc[mt][nt][3]);
      }
    }
    __syncthreads();

    // residual write: bias + relu + x + rz*y, coalesced fp32
    const int co_r = t >> 2;
    const int colb = (t & 3) * 4;
    const int cog = g * 128 + cb * 64 + co_r;
    const float bias = bT[cog];
    const size_t rowoff = ((size_t)b * 256 + cog) * 2048 + by * 256;
#pragma unroll
    for (int j = 0; j < 16; ++j) {
      const int col = colb + j * 16;
      const uint32_t* yp = (const uint32_t*)&sY[co_r * 264 + col];
      __nv_bfloat162 y0 = *(const __nv_bfloat162*)&yp[0];
      __nv_bfloat162 y1 = *(const __nv_bfloat162*)&yp[1];
      const float4 xv = *(const float4*)(x + rowoff + col);
      float4 o4;
      o4.x = xv.x + rz * fmaxf(__bfloat162float(y0.x) + bias, 0.f);
      o4.y = xv.y + rz * fmaxf(__bfloat162float(y0.y) + bias, 0.f);
      o4.z = xv.z + rz * fmaxf(__bfloat162float(y1.x) + bias, 0.f);
      o4.w = xv.w + rz * fmaxf(__bfloat162float(y1.y) + bias, 0.f);
      *(float4*)(out + rowoff + col) = o4;
    }
    __syncthreads();  // sY region reused as A-stage next cb
  }
}

// ---------------------------------------------------------------------------
extern "C" void kernel_launch(void* const* d_in, const int* in_sizes, int n_in,
                              void* d_out, int out_size) {
  (void)in_sizes; (void)n_in; (void)out_size;
  const float* x        = (const float*)d_in[0];
  const float* w1       = (const float*)d_in[1];
  const float* b1       = (const float*)d_in[2];
  const float* patterns = (const float*)d_in[3];
  const float* wT       = (const float*)d_in[4];
  const float* bT       = (const float*)d_in[5];
  const float* RZ       = (const float*)d_in[6];
  float* out            = (float*)d_out;

  cudaFuncSetAttribute(kgemm_scores,
                       cudaFuncAttributeMaxDynamicSharedMemorySize, 73728);
  cudaFuncSetAttribute(k45_fused,
                       cudaFuncAttributeMaxDynamicSharedMemorySize, 107520);

  kprep_all<<<608, 256>>>(w1, wT, patterns);
  k1_hmma<<<dim3(16, 2, 32), 256>>>(x, b1);
  kgemm_scores<<<dim3(4, 64), 256, 73728>>>();
  k3_softmax<<<kRows / 8, 256>>>();
  k45_fused<<<dim3(8, 32), 256, 107520>>>(x, bT, RZ, out);
}

// round 16
// speedup vs baseline: 1.0752x; 1.0389x over previous
#include <cuda_runtime.h>
#include <cuda_bf16.h>
#include <cstdint>

namespace {
constexpr int kB   = 16;
constexpr int kRows = kB * 512;  // 8192
}

// ---------------- scratch (device globals; no allocation) -------------------
__device__ __align__(16) __nv_bfloat16 g_w1b[512 * 128];       // w1 bf16
__device__ __align__(16) __nv_bfloat16 g_wTt[2 * 256 * 256];   // wT^T bf16 [g][co2][i]
__device__ __align__(16) __nv_bfloat16 g_hp[kRows * 1024];     // pooled hidden bf16
__device__ __align__(16) __nv_bfloat16 g_scb[kRows * 512];     // exp(scores) bf16
__device__ __align__(16) float         g_rowsum[kRows * 4];    // per (row, ntile) sums
__device__ __align__(16) __nv_bfloat16 g_pat[512 * 1024];      // patterns bf16 [m][lp]

// ---------------- PTX helpers ------------------------------------------------
__device__ __forceinline__ void cp_async16(uint32_t dst, const void* src) {
  asm volatile("cp.async.cg.shared.global [%0], [%1], 16;\n" ::"r"(dst), "l"(src));
}
#define CP_COMMIT() asm volatile("cp.async.commit_group;\n" ::: "memory")
#define CP_WAIT(n) asm volatile("cp.async.wait_group %0;\n" ::"n"(n) : "memory")

__device__ __forceinline__ void ldsm_x4(uint32_t (&r)[4], uint32_t addr) {
  asm volatile(
      "ldmatrix.sync.aligned.m8n8.x4.shared.b16 {%0,%1,%2,%3}, [%4];"
      : "=r"(r[0]), "=r"(r[1]), "=r"(r[2]), "=r"(r[3])
      : "r"(addr));
}
__device__ __forceinline__ void ldsm_x4_t(uint32_t (&r)[4], uint32_t addr) {
  asm volatile(
      "ldmatrix.sync.aligned.m8n8.x4.trans.shared.b16 {%0,%1,%2,%3}, [%4];"
      : "=r"(r[0]), "=r"(r[1]), "=r"(r[2]), "=r"(r[3])
      : "r"(addr));
}

__device__ __forceinline__ void mma_16816(float (&c)[4], const uint32_t (&a)[4],
                                          const uint32_t b0, const uint32_t b1) {
  asm volatile(
      "mma.sync.aligned.m16n8k16.row.col.f32.bf16.bf16.f32 "
      "{%0,%1,%2,%3}, {%4,%5,%6,%7}, {%8,%9}, {%0,%1,%2,%3};"
      : "+f"(c[0]), "+f"(c[1]), "+f"(c[2]), "+f"(c[3])
      : "r"(a[0]), "r"(a[1]), "r"(a[2]), "r"(a[3]), "r"(b0), "r"(b1));
}

__device__ __forceinline__ uint32_t pack_bf16(float a, float b) {
  __nv_bfloat162 p = __floats2bfloat162_rn(a, b);
  return *(uint32_t*)&p;
}

__device__ __forceinline__ void cvt_store16(char* d, const float4 (&v)[4]) {
  uint4 q0, q1;
  q0.x = pack_bf16(v[0].x, v[0].y); q0.y = pack_bf16(v[0].z, v[0].w);
  q0.z = pack_bf16(v[1].x, v[1].y); q0.w = pack_bf16(v[1].z, v[1].w);
  q1.x = pack_bf16(v[2].x, v[2].y); q1.y = pack_bf16(v[2].z, v[2].w);
  q1.z = pack_bf16(v[3].x, v[3].y); q1.w = pack_bf16(v[3].z, v[3].w);
  *(uint4*)d = q0;
  *((uint4*)d + 1) = q1;
}

// ---------------------------------------------------------------------------
// Prep: w1 -> g_w1b, pat -> g_pat (vec cvt); wT -> g_wTt via tiled transpose.
// ---------------------------------------------------------------------------
__global__ __launch_bounds__(256) void kprep_all(const float* __restrict__ w1,
                                                 const float* __restrict__ wT,
                                                 const float* __restrict__ pat) {
  __shared__ __align__(16) float sm[64 * 68];
  const int bid = blockIdx.x;
  const int t = threadIdx.x;
  if (bid < 64) {
    const int idx = (bid * 256 + t) * 4;
    const float4 v = *(const float4*)(w1 + idx);
    uint2 o;
    o.x = pack_bf16(v.x, v.y);
    o.y = pack_bf16(v.z, v.w);
    *(uint2*)&g_w1b[idx] = o;
  } else if (bid < 576) {
    const int i2 = ((bid - 64) * 256 + t) * 4;
    const float4 v = *(const float4*)(pat + i2);
    uint2 o;
    o.x = pack_bf16(v.x, v.y);
    o.y = pack_bf16(v.z, v.w);
    *(uint2*)&g_pat[i2] = o;
  } else {
    const int tb = bid - 576;
    const int g = tb >> 4, ti = (tb >> 2) & 3, tc = tb & 3;
    const float* src = wT + ((size_t)(g * 256 + ti * 64)) * 256 + tc * 64;
#pragma unroll
    for (int k = 0; k < 4; ++k) {
      const int idx = t + k * 256;
      const int r = idx >> 4, c4 = (idx & 15) * 4;
      *(float4*)&sm[r * 68 + c4] = *(const float4*)(src + (size_t)r * 256 + c4);
    }
    __syncthreads();
    __nv_bfloat16* dst = g_wTt + (size_t)g * 65536 + (size_t)(tc * 64) * 256 + ti * 64;
#pragma unroll
    for (int k = 0; k < 4; ++k) {
      const int idx = t + k * 256;
      const int orow = idx >> 4, ocol = (idx & 15) * 4;
      uint2 o;
      o.x = pack_bf16(sm[(ocol + 0) * 68 + orow], sm[(ocol + 1) * 68 + orow]);
      o.y = pack_bf16(sm[(ocol + 2) * 68 + orow], sm[(ocol + 3) * 68 + orow]);
      *(uint2*)&dst[(size_t)orow * 256 + ocol] = o;
    }
  }
}

// ---------------------------------------------------------------------------
// k1: HMMA grouped 1x1 conv + bias + ReLU + maxpool2 -> g_hp bf16 (validated)
// ---------------------------------------------------------------------------
__global__ __launch_bounds__(256) void k1_hmma(const float* __restrict__ x,
                                               const float* __restrict__ b1) {
  __shared__ __align__(16) char smem[37888];
  const int t = threadIdx.x, w = t >> 5, lid = t & 31;
  const int wm = w >> 2, wn = w & 3;
  const int bx = blockIdx.x, by = blockIdx.y, bz = blockIdx.z;
  const int b = bz >> 1, g = bz & 1;
  const uint32_t sAb = (uint32_t)__cvta_generic_to_shared(smem);
  const char* Ag = (const char*)(g_w1b + (size_t)(g * 256 + by * 128) * 128);
  const float* xB = x + ((size_t)(b * 256 + g * 128)) * 2048 + bx * 128;

  const int brow = t >> 3, bcq = t & 7;
  const float* xrow = xB + (size_t)brow * 2048 + bcq * 16;

  auto ldA = [&](int s, int it) {
#pragma unroll
    for (int i = 0; i < 2; ++i) {
      const int idx = t + i * 256;
      const int row = idx >> 2, ch = idx & 3;
      cp_async16(sAb + s * 10240 + row * 80 + ch * 16,
                 Ag + row * 256 + it * 64 + ch * 16);
    }
    CP_COMMIT();
  };

  float4 v[4];
  auto ldB = [&](int it) {
    const float4* p = (const float4*)(xrow + (size_t)it * 32 * 2048);
#pragma unroll
    for (int q = 0; q < 4; ++q) v[q] = p[q];
  };
  auto stB = [&](int s) {
    cvt_store16(smem + 20480 + s * 8704 + brow * 272 + bcq * 32, v);
  };

  float acc[4][4][4];
#pragma unroll
  for (int mt = 0; mt < 4; ++mt)
#pragma unroll
    for (int nt = 0; nt < 4; ++nt)
#pragma unroll
      for (int i = 0; i < 4; ++i) acc[mt][nt][i] = 0.f;

  ldA(0, 0);
  ldB(0);
  const uint32_t aAddr0 = sAb + (wm * 64 + (lid & 15)) * 80 + (lid >> 4) * 16;
  const uint32_t bAddr0 = sAb + 20480 +
      (((lid >> 3) & 1) * 8 + (lid & 7)) * 272 + (wn * 32 + (lid >> 4) * 8) * 2;

#pragma unroll 1
  for (int it = 0; it < 4; ++it) {
    if (it + 1 < 4) {
      ldA((it + 1) & 1, it + 1);
      CP_WAIT(1);
    } else {
      CP_WAIT(0);
    }
    stB(it & 1);
    __syncthreads();
    if (it + 1 < 4) ldB(it + 1);
    const uint32_t sOA = (uint32_t)(it & 1) * 10240;
    const uint32_t sOB = (uint32_t)(it & 1) * 8704;
#pragma unroll
    for (int ks = 0; ks < 2; ++ks) {
      uint32_t afr[4][4];
      uint32_t bfr[4][2];
#pragma unroll
      for (int mt = 0; mt < 4; ++mt)
        ldsm_x4(afr[mt], aAddr0 + sOA + mt * 16 * 80 + ks * 32);
#pragma unroll
      for (int nt2 = 0; nt2 < 2; ++nt2) {
        uint32_t r4[4];
        ldsm_x4_t(r4, bAddr0 + sOB + ks * 16 * 272 + nt2 * 32);
        bfr[nt2 * 2 + 0][0] = r4[0]; bfr[nt2 * 2 + 0][1] = r4[1];
        bfr[nt2 * 2 + 1][0] = r4[2]; bfr[nt2 * 2 + 1][1] = r4[3];
      }
#pragma unroll
      for (int mt = 0; mt < 4; ++mt)
#pragma unroll
        for (int nt = 0; nt < 4; ++nt)
          mma_16816(acc[mt][nt], afr[mt], bfr[nt][0], bfr[nt][1]);
    }
    __syncthreads();
  }

  __nv_bfloat16* sH = (__nv_bfloat16*)smem;  // [128][72]
#pragma unroll
  for (int mt = 0; mt < 4; ++mt) {
    const int m = wm * 64 + mt * 16 + (lid >> 2);
    const int og = g * 256 + by * 128 + m;
    const float bias0 = b1[og];
    const float bias1 = b1[og + 8];
#pragma unroll
    for (int nt = 0; nt < 4; ++nt) {
      const int np = wn * 16 + nt * 4 + (lid & 3);
      sH[m * 72 + np] =
          __float2bfloat16(fmaxf(fmaxf(acc[mt][nt][0], acc[mt][nt][1]) + bias0, 0.f));
      sH[(m + 8) * 72 + np] =
          __float2bfloat16(fmaxf(fmaxf(acc[mt][nt][2], acc[mt][nt][3]) + bias1, 0.f));
    }
  }
  __syncthreads();
  const size_t rowbase = (size_t)(b * 512 + g * 256 + by * 128);
  const int colbase = bx * 64;
#pragma unroll
  for (int p = 0; p < 4; ++p) {
    const int idx = t + p * 256;
    const int row = idx >> 3, ch = idx & 7;
    *(uint4*)&g_hp[(rowbase + row) * 1024 + colbase + ch * 8] =
        *(uint4*)&sH[row * 72 + ch * 8];
  }
}

// ---------------------------------------------------------------------------
// k2: exp-scores = exp(Hp @ P^T) (K=1024) -> g_scb bf16, + row partial sums
//     -> g_rowsum[row][ntile].  (softmax fused: no-max form, validated)
// ---------------------------------------------------------------------------
__global__ __launch_bounds__(256, 2) void kgemm_scores() {
  constexpr int ITERS = 16;
  extern __shared__ __align__(16) char smem[];  // A 2x18432 | B 2x18432
  const int t = threadIdx.x, w = t >> 5, lid = t & 31;
  const int wm = w >> 2, wn = w & 3;
  const int n0 = blockIdx.x * 128;
  const int r0 = blockIdx.y * 128;
  const uint32_t sAb = (uint32_t)__cvta_generic_to_shared(smem);
  constexpr uint32_t BOFF = 36864;
  const char* Ab = (const char*)(g_hp + (size_t)r0 * 1024);
  const char* Bb = (const char*)(g_pat + (size_t)n0 * 1024);

  auto load_tile = [&](int s, int it) {
#pragma unroll
    for (int i = 0; i < 4; ++i) {
      const int idx = t + i * 256;
      const int row = idx >> 3, ch = idx & 7;
      const size_t go = (size_t)row * 2048 + it * 128 + ch * 16;
      const uint32_t so = (uint32_t)s * 18432 + row * 144 + ch * 16;
      cp_async16(sAb + so, Ab + go);
      cp_async16(sAb + BOFF + so, Bb + go);
    }
    CP_COMMIT();
  };

  float acc[4][4][4];
#pragma unroll
  for (int mt = 0; mt < 4; ++mt)
#pragma unroll
    for (int nt = 0; nt < 4; ++nt)
#pragma unroll
      for (int i = 0; i < 4; ++i) acc[mt][nt][i] = 0.f;

  load_tile(0, 0);
  const uint32_t aAddr0 = sAb + (wm * 64 + (lid & 15)) * 144 + (lid >> 4) * 16;
  const uint32_t bAddr0 = sAb + BOFF +
      (wn * 32 + ((lid >> 4) ? 8 : 0) + (lid & 7)) * 144 + ((lid >> 3) & 1) * 16;

#pragma unroll 1
  for (int it = 0; it < ITERS; ++it) {
    CP_WAIT(0);
    __syncthreads();
    if (it + 1 < ITERS) load_tile((it + 1) & 1, it + 1);
    const uint32_t sO = (uint32_t)(it & 1) * 18432;
#pragma unroll
    for (int ks = 0; ks < 4; ++ks) {
      uint32_t afr[4][4];
      uint32_t bfr[4][2];
#pragma unroll
      for (int mt = 0; mt < 4; ++mt)
        ldsm_x4(afr[mt], aAddr0 + sO + mt * 16 * 144 + ks * 32);
#pragma unroll
      for (int nt2 = 0; nt2 < 2; ++nt2) {
        uint32_t r4[4];
        ldsm_x4(r4, bAddr0 + sO + nt2 * 16 * 144 + ks * 32);
        bfr[nt2 * 2 + 0][0] = r4[0]; bfr[nt2 * 2 + 0][1] = r4[1];
        bfr[nt2 * 2 + 1][0] = r4[2]; bfr[nt2 * 2 + 1][1] = r4[3];
      }
#pragma unroll
      for (int mt = 0; mt < 4; ++mt)
#pragma unroll
        for (int nt = 0; nt < 4; ++nt)
          mma_16816(acc[mt][nt], afr[mt], bfr[nt][0], bfr[nt][1]);
    }
  }

  // epilogue: exp + bf16 store + row partial sums
  __nv_bfloat16* Crow = g_scb + (size_t)(r0 + wm * 64) * 512 + n0 + wn * 32;
  const int rr = lid >> 2;
  const int cc = (lid & 3) * 2;
  float rs0[4], rs1[4];
#pragma unroll
  for (int mt = 0; mt < 4; ++mt) { rs0[mt] = 0.f; rs1[mt] = 0.f; }
#pragma unroll
  for (int mt = 0; mt < 4; ++mt)
#pragma unroll
    for (int nt = 0; nt < 4; ++nt) {
      const float e0 = __expf(acc[mt][nt][0]);
      const float e1 = __expf(acc[mt][nt][1]);
      const float e2 = __expf(acc[mt][nt][2]);
      const float e3 = __expf(acc[mt][nt][3]);
      *(uint32_t*)&Crow[(size_t)(mt * 16 + rr) * 512 + nt * 8 + cc] =
          pack_bf16(e0, e1);
      *(uint32_t*)&Crow[(size_t)(mt * 16 + rr + 8) * 512 + nt * 8 + cc] =
          pack_bf16(e2, e3);
      rs0[mt] += e0 + e1;
      rs1[mt] += e2 + e3;
    }
#pragma unroll
  for (int mt = 0; mt < 4; ++mt) {
    rs0[mt] += __shfl_xor_sync(0xffffffffu, rs0[mt], 1);
    rs0[mt] += __shfl_xor_sync(0xffffffffu, rs0[mt], 2);
    rs1[mt] += __shfl_xor_sync(0xffffffffu, rs1[mt], 1);
    rs1[mt] += __shfl_xor_sync(0xffffffffu, rs1[mt], 2);
  }
  __syncthreads();  // stage smem reads done; reuse as reduction buffer
  float* sums = (float*)smem;  // [128][4]
  if ((lid & 3) == 0) {
#pragma unroll
    for (int mt = 0; mt < 4; ++mt) {
      sums[(wm * 64 + mt * 16 + rr) * 4 + wn] = rs0[mt];
      sums[(wm * 64 + mt * 16 + rr + 8) * 4 + wn] = rs1[mt];
    }
  }
  __syncthreads();
  if (t < 128) {
    const float4 s4 = *(const float4*)&sums[t * 4];
    g_rowsum[(size_t)(r0 + t) * 4 + blockIdx.x] = s4.x + s4.y + s4.z + s4.w;
  }
}

// ---------------------------------------------------------------------------
// k45: FUSED (normalize + retrieval) + ConvT + bias + ReLU + residual.
// Phase1 consumes exp-scores and scales hr rows by 1/rowsum at store.
// ---------------------------------------------------------------------------
__global__ __launch_bounds__(256, 2) void k45_fused(
    const float* __restrict__ x, const float* __restrict__ bT,
    const float* __restrict__ rzp, float* __restrict__ out) {
  extern __shared__ __align__(16) char smem[];
  const int t = threadIdx.x, w = t >> 5, lid = t & 31;
  const int wm = w >> 2, wn = w & 3;
  const int by = blockIdx.x, bz = blockIdx.y;
  const int b = bz >> 1, g = bz & 1;
  const int lp0 = by * 128;
  const uint32_t sAb = (uint32_t)__cvta_generic_to_shared(smem);
  constexpr uint32_t P1_BOFF = 20480;
  constexpr uint32_t HR = 37888;
  __nv_bfloat16* hrp = (__nv_bfloat16*)(smem + HR);

  const char* Bb1 = (const char*)(g_pat + lp0);

  // ---------------- Phase 1: two 128-c halves of hr ----------------
#pragma unroll 1
  for (int half = 0; half < 2; ++half) {
    const int r0 = b * 512 + g * 256 + half * 128;
    const char* Ab = (const char*)(g_scb + (size_t)r0 * 512);

    auto load_tile = [&](int s, int it) {
#pragma unroll
      for (int i = 0; i < 2; ++i) {
        const int idx = t + i * 256;
        const int row = idx >> 2, ch = idx & 3;
        cp_async16(sAb + s * 10240 + row * 80 + ch * 16,
                   Ab + (size_t)row * 1024 + it * 64 + ch * 16);
      }
#pragma unroll
      for (int i = 0; i < 2; ++i) {
        const int idx = t + i * 256;
        const int row = idx >> 4, ch = idx & 15;
        cp_async16(sAb + P1_BOFF + s * 8704 + row * 272 + ch * 16,
                   Bb1 + (size_t)(it * 32 + row) * 2048 + ch * 16);
      }
      CP_COMMIT();
    };

    float acc[4][4][4];
#pragma unroll
    for (int mt = 0; mt < 4; ++mt)
#pragma unroll
      for (int nt = 0; nt < 4; ++nt)
#pragma unroll
        for (int i = 0; i < 4; ++i) acc[mt][nt][i] = 0.f;

    __syncthreads();
    load_tile(0, 0);
    const uint32_t aAddr0 = sAb + (wm * 64 + (lid & 15)) * 80 + (lid >> 4) * 16;
    const uint32_t bAddr0 = sAb + P1_BOFF +
        (((lid >> 3) & 1) * 8 + (lid & 7)) * 272 + (wn * 32 + (lid >> 4) * 8) * 2;

#pragma unroll 1
    for (int it = 0; it < 16; ++it) {
      CP_WAIT(0);
      __syncthreads();
      if (it + 1 < 16) load_tile((it + 1) & 1, it + 1);
      const uint32_t sOA = (uint32_t)(it & 1) * 10240;
      const uint32_t sOB = (uint32_t)(it & 1) * 8704;
#pragma unroll
      for (int ks = 0; ks < 2; ++ks) {
        uint32_t afr[4][4];
        uint32_t bfr[4][2];
#pragma unroll
        for (int mt = 0; mt < 4; ++mt)
          ldsm_x4(afr[mt], aAddr0 + sOA + mt * 16 * 80 + ks * 32);
#pragma unroll
        for (int nt2 = 0; nt2 < 2; ++nt2) {
          uint32_t r4[4];
          ldsm_x4_t(r4, bAddr0 + sOB + ks * 16 * 272 + nt2 * 32);
          bfr[nt2 * 2 + 0][0] = r4[0]; bfr[nt2 * 2 + 0][1] = r4[1];
          bfr[nt2 * 2 + 1][0] = r4[2]; bfr[nt2 * 2 + 1][1] = r4[3];
        }
#pragma unroll
        for (int mt = 0; mt < 4; ++mt)
#pragma unroll
          for (int nt = 0; nt < 4; ++nt)
            mma_16816(acc[mt][nt], afr[mt], bfr[nt][0], bfr[nt][1]);
      }
    }

    // 1/rowsum for the 128 rows of this half (stage smem reuse)
    __syncthreads();
    float* invb = (float*)smem;
    if (t < 128) {
      const float4 s4 = *(const float4*)&g_rowsum[(size_t)(r0 + t) * 4];
      invb[t] = 1.f / (s4.x + s4.y + s4.z + s4.w);
    }
    __syncthreads();

    // store acc*inv -> hr[c][lp] bf16
#pragma unroll
    for (int mt = 0; mt < 4; ++mt) {
      const int lr = wm * 64 + mt * 16 + (lid >> 2);
      const int c = half * 128 + lr;
      const float iv1 = invb[lr];
      const float iv2 = invb[lr + 8];
#pragma unroll
      for (int nt = 0; nt < 4; ++nt) {
        const int lp = wn * 32 + nt * 8 + (lid & 3) * 2;
        *(uint32_t*)((char*)hrp + c * 272 + lp * 2) =
            pack_bf16(acc[mt][nt][0] * iv1, acc[mt][nt][1] * iv1);
        *(uint32_t*)((char*)hrp + (c + 8) * 272 + lp * 2) =
            pack_bf16(acc[mt][nt][2] * iv2, acc[mt][nt][3] * iv2);
      }
    }
  }
  __syncthreads();

  // ---------------- Phase 2: two 128-co2 halves of y ----------------
  const float rz = rzp[0];
  const uint32_t aAddr2 = sAb + (wm * 64 + (lid & 15)) * 144 + (lid >> 4) * 16;
  const uint32_t bAddr2 = sAb + HR +
      (((lid >> 3) & 1) * 8 + (lid & 7)) * 272 + (wn * 32 + (lid >> 4) * 8) * 2;

#pragma unroll 1
  for (int cb = 0; cb < 2; ++cb) {
    const char* Awt =
        (const char*)(g_wTt + (size_t)g * 65536 + (size_t)cb * 128 * 256);

    auto loadA2 = [&](int s, int it) {
#pragma unroll
      for (int i = 0; i < 4; ++i) {
        const int idx = t + i * 256;
        const int row = idx >> 3, ch = idx & 7;
        cp_async16(sAb + s * 18432 + row * 144 + ch * 16,
                   Awt + (size_t)row * 512 + it * 128 + ch * 16);
      }
      CP_COMMIT();
    };

    float acc[4][4][4];
#pragma unroll
    for (int mt = 0; mt < 4; ++mt)
#pragma unroll
      for (int nt = 0; nt < 4; ++nt)
#pragma unroll
        for (int i = 0; i < 4; ++i) acc[mt][nt][i] = 0.f;

    loadA2(0, 0);

#pragma unroll 1
    for (int it = 0; it < 4; ++it) {
      CP_WAIT(0);
      __syncthreads();
      if (it + 1 < 4) loadA2((it + 1) & 1, it + 1);
      const uint32_t sOA = (uint32_t)(it & 1) * 18432;
      const uint32_t bIt = (uint32_t)(it * 64) * 272;
#pragma unroll
      for (int ks = 0; ks < 4; ++ks) {
        uint32_t afr[4][4];
        uint32_t bfr[4][2];
#pragma unroll
        for (int mt = 0; mt < 4; ++mt)
          ldsm_x4(afr[mt], aAddr2 + sOA + mt * 16 * 144 + ks * 32);
#pragma unroll
        for (int nt2 = 0; nt2 < 2; ++nt2) {
          uint32_t r4[4];
          ldsm_x4_t(r4, bAddr2 + bIt + ks * 16 * 272 + nt2 * 32);
          bfr[nt2 * 2 + 0][0] = r4[0]; bfr[nt2 * 2 + 0][1] = r4[1];
          bfr[nt2 * 2 + 1][0] = r4[2]; bfr[nt2 * 2 + 1][1] = r4[3];
        }
#pragma unroll
        for (int mt = 0; mt < 4; ++mt)
#pragma unroll
          for (int nt = 0; nt < 4; ++nt)
            mma_16816(acc[mt][nt], afr[mt], bfr[nt][0], bfr[nt][1]);
      }
    }
    __syncthreads();  // A-stage reads done -> safe to reuse as sY

    // stage raw y (pre-bias) into sY[co 64][l 264] bf16
    __nv_bfloat16* sY = (__nv_bfloat16*)smem;
#pragma unroll
    for (int mt = 0; mt < 4; ++mt) {
      const int r1 = wm * 64 + mt * 16 + (lid >> 2);
      const int r2 = r1 + 8;
#pragma unroll
      for (int nt = 0; nt < 4; ++nt) {
        const int lp = wn * 32 + nt * 8 + (lid & 3) * 2;
        sY[(r1 >> 1) * 264 + 2 * lp + (r1 & 1)] = __float2bfloat16(acc[mt][nt][0]);
        sY[(r1 >> 1) * 264 + 2 * (lp + 1) + (r1 & 1)] = __float2bfloat16(acc[mt][nt][1]);
        sY[(r2 >> 1) * 264 + 2 * lp + (r2 & 1)] = __float2bfloat16(acc[mt][nt][2]);
        sY[(r2 >> 1) * 264 + 2 * (lp + 1) + (r2 & 1)] = __float2bfloat16(acc[mt][nt][3]);
      }
    }
    __syncthreads();

    // residual write: bias + relu + x + rz*y, coalesced fp32
    const int co_r = t >> 2;
    const int colb = (t & 3) * 4;
    const int cog = g * 128 + cb * 64 + co_r;
    const float bias = bT[cog];
    const size_t rowoff = ((size_t)b * 256 + cog) * 2048 + by * 256;
#pragma unroll
    for (int j = 0; j < 16; ++j) {
      const int col = colb + j * 16;
      const uint32_t* yp = (const uint32_t*)&sY[co_r * 264 + col];
      __nv_bfloat162 y0 = *(const __nv_bfloat162*)&yp[0];
      __nv_bfloat162 y1 = *(const __nv_bfloat162*)&yp[1];
      const float4 xv = *(const float4*)(x + rowoff + col);
      float4 o4;
      o4.x = xv.x + rz * fmaxf(__bfloat162float(y0.x) + bias, 0.f);
      o4.y = xv.y + rz * fmaxf(__bfloat162float(y0.y) + bias, 0.f);
      o4.z = xv.z + rz * fmaxf(__bfloat162float(y1.x) + bias, 0.f);
      o4.w = xv.w + rz * fmaxf(__bfloat162float(y1.y) + bias, 0.f);
      *(float4*)(out + rowoff + col) = o4;
    }
    __syncthreads();  // sY region reused as A-stage next cb
  }
}

// ---------------------------------------------------------------------------
extern "C" void kernel_launch(void* const* d_in, const int* in_sizes, int n_in,
                              void* d_out, int out_size) {
  (void)in_sizes; (void)n_in; (void)out_size;
  const float* x        = (const float*)d_in[0];
  const float* w1       = (const float*)d_in[1];
  const float* b1       = (const float*)d_in[2];
  const float* patterns = (const float*)d_in[3];
  const float* wT       = (const float*)d_in[4];
  const float* bT       = (const float*)d_in[5];
  const float* RZ       = (const float*)d_in[6];
  float* out            = (float*)d_out;

  cudaFuncSetAttribute(kgemm_scores,
                       cudaFuncAttributeMaxDynamicSharedMemorySize, 73728);
  cudaFuncSetAttribute(k45_fused,
                       cudaFuncAttributeMaxDynamicSharedMemorySize, 107520);

  kprep_all<<<608, 256>>>(w1, wT, patterns);
  k1_hmma<<<dim3(16, 2, 32), 256>>>(x, b1);
  kgemm_scores<<<dim3(4, 64), 256, 73728>>>();
  k45_fused<<<dim3(8, 32), 256, 107520>>>(x, bT, RZ, out);
}

// round 17
// speedup vs baseline: 1.0897x; 1.0135x over previous
#include <cuda_runtime.h>
#include <cuda_bf16.h>
#include <cstdint>

namespace {
constexpr int kB   = 16;
constexpr int kRows = kB * 512;  // 8192
}

// ---------------- scratch (device globals; no allocation) -------------------
__device__ __align__(16) __nv_bfloat16 g_w1b[512 * 128];       // w1 bf16
__device__ __align__(16) __nv_bfloat16 g_wTt[2 * 256 * 256];   // wT^T bf16 [g][co2][i]
__device__ __align__(16) __nv_bfloat16 g_hp[kRows * 1024];     // pooled hidden bf16
__device__ __align__(16) __nv_bfloat16 g_scb[kRows * 512];     // exp(scores) bf16
__device__ __align__(16) float         g_rowsum[kRows * 4];    // per (row, ntile) sums
__device__ __align__(16) __nv_bfloat16 g_pat[512 * 1024];      // patterns bf16 [m][lp]

// ---------------- PTX helpers ------------------------------------------------
__device__ __forceinline__ void cp_async16(uint32_t dst, const void* src) {
  asm volatile("cp.async.cg.shared.global [%0], [%1], 16;\n" ::"r"(dst), "l"(src));
}
#define CP_COMMIT() asm volatile("cp.async.commit_group;\n" ::: "memory")
#define CP_WAIT(n) asm volatile("cp.async.wait_group %0;\n" ::"n"(n) : "memory")

__device__ __forceinline__ void ldsm_x4(uint32_t (&r)[4], uint32_t addr) {
  asm volatile(
      "ldmatrix.sync.aligned.m8n8.x4.shared.b16 {%0,%1,%2,%3}, [%4];"
      : "=r"(r[0]), "=r"(r[1]), "=r"(r[2]), "=r"(r[3])
      : "r"(addr));
}
__device__ __forceinline__ void ldsm_x4_t(uint32_t (&r)[4], uint32_t addr) {
  asm volatile(
      "ldmatrix.sync.aligned.m8n8.x4.trans.shared.b16 {%0,%1,%2,%3}, [%4];"
      : "=r"(r[0]), "=r"(r[1]), "=r"(r[2]), "=r"(r[3])
      : "r"(addr));
}

__device__ __forceinline__ void mma_16816(float (&c)[4], const uint32_t (&a)[4],
                                          const uint32_t b0, const uint32_t b1) {
  asm volatile(
      "mma.sync.aligned.m16n8k16.row.col.f32.bf16.bf16.f32 "
      "{%0,%1,%2,%3}, {%4,%5,%6,%7}, {%8,%9}, {%0,%1,%2,%3};"
      : "+f"(c[0]), "+f"(c[1]), "+f"(c[2]), "+f"(c[3])
      : "r"(a[0]), "r"(a[1]), "r"(a[2]), "r"(a[3]), "r"(b0), "r"(b1));
}

__device__ __forceinline__ uint32_t pack_bf16(float a, float b) {
  __nv_bfloat162 p = __floats2bfloat162_rn(a, b);
  return *(uint32_t*)&p;
}

__device__ __forceinline__ void cvt_store16(char* d, const float4 (&v)[4]) {
  uint4 q0, q1;
  q0.x = pack_bf16(v[0].x, v[0].y); q0.y = pack_bf16(v[0].z, v[0].w);
  q0.z = pack_bf16(v[1].x, v[1].y); q0.w = pack_bf16(v[1].z, v[1].w);
  q1.x = pack_bf16(v[2].x, v[2].y); q1.y = pack_bf16(v[2].z, v[2].w);
  q1.z = pack_bf16(v[3].x, v[3].y); q1.w = pack_bf16(v[3].z, v[3].w);
  *(uint4*)d = q0;
  *((uint4*)d + 1) = q1;
}

// ---------------------------------------------------------------------------
// Prep: w1 -> g_w1b, pat -> g_pat (vec cvt); wT -> g_wTt via tiled transpose.
// ---------------------------------------------------------------------------
__global__ __launch_bounds__(256) void kprep_all(const float* __restrict__ w1,
                                                 const float* __restrict__ wT,
                                                 const float* __restrict__ pat) {
  __shared__ __align__(16) float sm[64 * 68];
  const int bid = blockIdx.x;
  const int t = threadIdx.x;
  if (bid < 64) {
    const int idx = (bid * 256 + t) * 4;
    const float4 v = *(const float4*)(w1 + idx);
    uint2 o;
    o.x = pack_bf16(v.x, v.y);
    o.y = pack_bf16(v.z, v.w);
    *(uint2*)&g_w1b[idx] = o;
  } else if (bid < 576) {
    const int i2 = ((bid - 64) * 256 + t) * 4;
    const float4 v = *(const float4*)(pat + i2);
    uint2 o;
    o.x = pack_bf16(v.x, v.y);
    o.y = pack_bf16(v.z, v.w);
    *(uint2*)&g_pat[i2] = o;
  } else {
    const int tb = bid - 576;
    const int g = tb >> 4, ti = (tb >> 2) & 3, tc = tb & 3;
    const float* src = wT + ((size_t)(g * 256 + ti * 64)) * 256 + tc * 64;
#pragma unroll
    for (int k = 0; k < 4; ++k) {
      const int idx = t + k * 256;
      const int r = idx >> 4, c4 = (idx & 15) * 4;
      *(float4*)&sm[r * 68 + c4] = *(const float4*)(src + (size_t)r * 256 + c4);
    }
    __syncthreads();
    __nv_bfloat16* dst = g_wTt + (size_t)g * 65536 + (size_t)(tc * 64) * 256 + ti * 64;
#pragma unroll
    for (int k = 0; k < 4; ++k) {
      const int idx = t + k * 256;
      const int orow = idx >> 4, ocol = (idx & 15) * 4;
      uint2 o;
      o.x = pack_bf16(sm[(ocol + 0) * 68 + orow], sm[(ocol + 1) * 68 + orow]);
      o.y = pack_bf16(sm[(ocol + 2) * 68 + orow], sm[(ocol + 3) * 68 + orow]);
      *(uint2*)&dst[(size_t)orow * 256 + ocol] = o;
    }
  }
}

// ---------------------------------------------------------------------------
// k1: HMMA grouped 1x1 conv + bias + ReLU + maxpool2 -> g_hp bf16 (validated)
// ---------------------------------------------------------------------------
__global__ __launch_bounds__(256) void k1_hmma(const float* __restrict__ x,
                                               const float* __restrict__ b1) {
  __shared__ __align__(16) char smem[37888];
  const int t = threadIdx.x, w = t >> 5, lid = t & 31;
  const int wm = w >> 2, wn = w & 3;
  const int bx = blockIdx.x, by = blockIdx.y, bz = blockIdx.z;
  const int b = bz >> 1, g = bz & 1;
  const uint32_t sAb = (uint32_t)__cvta_generic_to_shared(smem);
  const char* Ag = (const char*)(g_w1b + (size_t)(g * 256 + by * 128) * 128);
  const float* xB = x + ((size_t)(b * 256 + g * 128)) * 2048 + bx * 128;

  const int brow = t >> 3, bcq = t & 7;
  const float* xrow = xB + (size_t)brow * 2048 + bcq * 16;

  auto ldA = [&](int s, int it) {
#pragma unroll
    for (int i = 0; i < 2; ++i) {
      const int idx = t + i * 256;
      const int row = idx >> 2, ch = idx & 3;
      cp_async16(sAb + s * 10240 + row * 80 + ch * 16,
                 Ag + row * 256 + it * 64 + ch * 16);
    }
    CP_COMMIT();
  };

  float4 v[4];
  auto ldB = [&](int it) {
    const float4* p = (const float4*)(xrow + (size_t)it * 32 * 2048);
#pragma unroll
    for (int q = 0; q < 4; ++q) v[q] = p[q];
  };
  auto stB = [&](int s) {
    cvt_store16(smem + 20480 + s * 8704 + brow * 272 + bcq * 32, v);
  };

  float acc[4][4][4];
#pragma unroll
  for (int mt = 0; mt < 4; ++mt)
#pragma unroll
    for (int nt = 0; nt < 4; ++nt)
#pragma unroll
      for (int i = 0; i < 4; ++i) acc[mt][nt][i] = 0.f;

  ldA(0, 0);
  ldB(0);
  const uint32_t aAddr0 = sAb + (wm * 64 + (lid & 15)) * 80 + (lid >> 4) * 16;
  const uint32_t bAddr0 = sAb + 20480 +
      (((lid >> 3) & 1) * 8 + (lid & 7)) * 272 + (wn * 32 + (lid >> 4) * 8) * 2;

#pragma unroll 1
  for (int it = 0; it < 4; ++it) {
    if (it + 1 < 4) {
      ldA((it + 1) & 1, it + 1);
      CP_WAIT(1);
    } else {
      CP_WAIT(0);
    }
    stB(it & 1);
    __syncthreads();
    if (it + 1 < 4) ldB(it + 1);
    const uint32_t sOA = (uint32_t)(it & 1) * 10240;
    const uint32_t sOB = (uint32_t)(it & 1) * 8704;
#pragma unroll
    for (int ks = 0; ks < 2; ++ks) {
      uint32_t afr[4][4];
      uint32_t bfr[4][2];
#pragma unroll
      for (int mt = 0; mt < 4; ++mt)
        ldsm_x4(afr[mt], aAddr0 + sOA + mt * 16 * 80 + ks * 32);
#pragma unroll
      for (int nt2 = 0; nt2 < 2; ++nt2) {
        uint32_t r4[4];
        ldsm_x4_t(r4, bAddr0 + sOB + ks * 16 * 272 + nt2 * 32);
        bfr[nt2 * 2 + 0][0] = r4[0]; bfr[nt2 * 2 + 0][1] = r4[1];
        bfr[nt2 * 2 + 1][0] = r4[2]; bfr[nt2 * 2 + 1][1] = r4[3];
      }
#pragma unroll
      for (int mt = 0; mt < 4; ++mt)
#pragma unroll
        for (int nt = 0; nt < 4; ++nt)
          mma_16816(acc[mt][nt], afr[mt], bfr[nt][0], bfr[nt][1]);
    }
    __syncthreads();
  }

  __nv_bfloat16* sH = (__nv_bfloat16*)smem;  // [128][72]
#pragma unroll
  for (int mt = 0; mt < 4; ++mt) {
    const int m = wm * 64 + mt * 16 + (lid >> 2);
    const int og = g * 256 + by * 128 + m;
    const float bias0 = b1[og];
    const float bias1 = b1[og + 8];
#pragma unroll
    for (int nt = 0; nt < 4; ++nt) {
      const int np = wn * 16 + nt * 4 + (lid & 3);
      sH[m * 72 + np] =
          __float2bfloat16(fmaxf(fmaxf(acc[mt][nt][0], acc[mt][nt][1]) + bias0, 0.f));
      sH[(m + 8) * 72 + np] =
          __float2bfloat16(fmaxf(fmaxf(acc[mt][nt][2], acc[mt][nt][3]) + bias1, 0.f));
    }
  }
  __syncthreads();
  const size_t rowbase = (size_t)(b * 512 + g * 256 + by * 128);
  const int colbase = bx * 64;
#pragma unroll
  for (int p = 0; p < 4; ++p) {
    const int idx = t + p * 256;
    const int row = idx >> 3, ch = idx & 7;
    *(uint4*)&g_hp[(rowbase + row) * 1024 + colbase + ch * 8] =
        *(uint4*)&sH[row * 72 + ch * 8];
  }
}

// ---------------------------------------------------------------------------
// k2: exp-scores = exp(Hp @ P^T) (K=1024) -> g_scb bf16, + row partial sums
// ---------------------------------------------------------------------------
__global__ __launch_bounds__(256, 2) void kgemm_scores() {
  constexpr int ITERS = 16;
  extern __shared__ __align__(16) char smem[];  // A 2x18432 | B 2x18432
  const int t = threadIdx.x, w = t >> 5, lid = t & 31;
  const int wm = w >> 2, wn = w & 3;
  const int n0 = blockIdx.x * 128;
  const int r0 = blockIdx.y * 128;
  const uint32_t sAb = (uint32_t)__cvta_generic_to_shared(smem);
  constexpr uint32_t BOFF = 36864;
  const char* Ab = (const char*)(g_hp + (size_t)r0 * 1024);
  const char* Bb = (const char*)(g_pat + (size_t)n0 * 1024);

  auto load_tile = [&](int s, int it) {
#pragma unroll
    for (int i = 0; i < 4; ++i) {
      const int idx = t + i * 256;
      const int row = idx >> 3, ch = idx & 7;
      const size_t go = (size_t)row * 2048 + it * 128 + ch * 16;
      const uint32_t so = (uint32_t)s * 18432 + row * 144 + ch * 16;
      cp_async16(sAb + so, Ab + go);
      cp_async16(sAb + BOFF + so, Bb + go);
    }
    CP_COMMIT();
  };

  float acc[4][4][4];
#pragma unroll
  for (int mt = 0; mt < 4; ++mt)
#pragma unroll
    for (int nt = 0; nt < 4; ++nt)
#pragma unroll
      for (int i = 0; i < 4; ++i) acc[mt][nt][i] = 0.f;

  load_tile(0, 0);
  const uint32_t aAddr0 = sAb + (wm * 64 + (lid & 15)) * 144 + (lid >> 4) * 16;
  const uint32_t bAddr0 = sAb + BOFF +
      (wn * 32 + ((lid >> 4) ? 8 : 0) + (lid & 7)) * 144 + ((lid >> 3) & 1) * 16;

#pragma unroll 1
  for (int it = 0; it < ITERS; ++it) {
    CP_WAIT(0);
    __syncthreads();
    if (it + 1 < ITERS) load_tile((it + 1) & 1, it + 1);
    const uint32_t sO = (uint32_t)(it & 1) * 18432;
#pragma unroll
    for (int ks = 0; ks < 4; ++ks) {
      uint32_t afr[4][4];
      uint32_t bfr[4][2];
#pragma unroll
      for (int mt = 0; mt < 4; ++mt)
        ldsm_x4(afr[mt], aAddr0 + sO + mt * 16 * 144 + ks * 32);
#pragma unroll
      for (int nt2 = 0; nt2 < 2; ++nt2) {
        uint32_t r4[4];
        ldsm_x4(r4, bAddr0 + sO + nt2 * 16 * 144 + ks * 32);
        bfr[nt2 * 2 + 0][0] = r4[0]; bfr[nt2 * 2 + 0][1] = r4[1];
        bfr[nt2 * 2 + 1][0] = r4[2]; bfr[nt2 * 2 + 1][1] = r4[3];
      }
#pragma unroll
      for (int mt = 0; mt < 4; ++mt)
#pragma unroll
        for (int nt = 0; nt < 4; ++nt)
          mma_16816(acc[mt][nt], afr[mt], bfr[nt][0], bfr[nt][1]);
    }
  }

  // epilogue: exp + bf16 store + row partial sums
  __nv_bfloat16* Crow = g_scb + (size_t)(r0 + wm * 64) * 512 + n0 + wn * 32;
  const int rr = lid >> 2;
  const int cc = (lid & 3) * 2;
  float rs0[4], rs1[4];
#pragma unroll
  for (int mt = 0; mt < 4; ++mt) { rs0[mt] = 0.f; rs1[mt] = 0.f; }
#pragma unroll
  for (int mt = 0; mt < 4; ++mt)
#pragma unroll
    for (int nt = 0; nt < 4; ++nt) {
      const float e0 = __expf(acc[mt][nt][0]);
      const float e1 = __expf(acc[mt][nt][1]);
      const float e2 = __expf(acc[mt][nt][2]);
      const float e3 = __expf(acc[mt][nt][3]);
      *(uint32_t*)&Crow[(size_t)(mt * 16 + rr) * 512 + nt * 8 + cc] =
          pack_bf16(e0, e1);
      *(uint32_t*)&Crow[(size_t)(mt * 16 + rr + 8) * 512 + nt * 8 + cc] =
          pack_bf16(e2, e3);
      rs0[mt] += e0 + e1;
      rs1[mt] += e2 + e3;
    }
#pragma unroll
  for (int mt = 0; mt < 4; ++mt) {
    rs0[mt] += __shfl_xor_sync(0xffffffffu, rs0[mt], 1);
    rs0[mt] += __shfl_xor_sync(0xffffffffu, rs0[mt], 2);
    rs1[mt] += __shfl_xor_sync(0xffffffffu, rs1[mt], 1);
    rs1[mt] += __shfl_xor_sync(0xffffffffu, rs1[mt], 2);
  }
  __syncthreads();
  float* sums = (float*)smem;  // [128][4]
  if ((lid & 3) == 0) {
#pragma unroll
    for (int mt = 0; mt < 4; ++mt) {
      sums[(wm * 64 + mt * 16 + rr) * 4 + wn] = rs0[mt];
      sums[(wm * 64 + mt * 16 + rr + 8) * 4 + wn] = rs1[mt];
    }
  }
  __syncthreads();
  if (t < 128) {
    const float4 s4 = *(const float4*)&sums[t * 4];
    g_rowsum[(size_t)(r0 + t) * 4 + blockIdx.x] = s4.x + s4.y + s4.z + s4.w;
  }
}

// ---------------------------------------------------------------------------
// k45: FUSED (normalize + retrieval) + ConvT + bias + ReLU + residual.
// Phase1 now BK=64 (8 iters, 4 k16) with B-stages aliased into HR-high
// (hr rows 128..255 region), overwritten only after all B reads complete.
// smem 106496: A stages [0,36864) | HR [36864,106496) (256 rows x 272B)
//   B stages (phase1 only) at HR+34816, 2x17408 = exactly hr rows 128..255.
// ---------------------------------------------------------------------------
__global__ __launch_bounds__(256, 2) void k45_fused(
    const float* __restrict__ x, const float* __restrict__ bT,
    const float* __restrict__ rzp, float* __restrict__ out) {
  extern __shared__ __align__(16) char smem[];
  const int t = threadIdx.x, w = t >> 5, lid = t & 31;
  const int wm = w >> 2, wn = w & 3;
  const int by = blockIdx.x, bz = blockIdx.y;
  const int b = bz >> 1, g = bz & 1;
  const int lp0 = by * 128;
  const uint32_t sAb = (uint32_t)__cvta_generic_to_shared(smem);
  constexpr uint32_t HR = 36864;           // hr buffer (256 x 272B)
  constexpr uint32_t P1_B = HR + 34816;    // phase1 B stages (alias hr rows 128+)
  __nv_bfloat16* hrp = (__nv_bfloat16*)(smem + HR);

  const char* Bb1 = (const char*)(g_pat + lp0);

  // ---------------- Phase 1: two 128-c halves of hr, BK=64 ----------------
#pragma unroll 1
  for (int half = 0; half < 2; ++half) {
    const int r0 = b * 512 + g * 256 + half * 128;
    const char* Ab = (const char*)(g_scb + (size_t)r0 * 512);

    auto load_tile = [&](int s, int it) {
#pragma unroll
      for (int i = 0; i < 4; ++i) {  // A: 128 rows x 128B
        const int idx = t + i * 256;
        const int row = idx >> 3, ch = idx & 7;
        cp_async16(sAb + s * 18432 + row * 144 + ch * 16,
                   Ab + (size_t)row * 1024 + it * 128 + ch * 16);
      }
#pragma unroll
      for (int i = 0; i < 4; ++i) {  // B: 64 m-rows x 256B (trans)
        const int idx = t + i * 256;
        const int row = idx >> 4, ch = idx & 15;
        cp_async16(sAb + P1_B + s * 17408 + row * 272 + ch * 16,
                   Bb1 + (size_t)(it * 64 + row) * 2048 + ch * 16);
      }
      CP_COMMIT();
    };

    float acc[4][4][4];
#pragma unroll
    for (int mt = 0; mt < 4; ++mt)
#pragma unroll
      for (int nt = 0; nt < 4; ++nt)
#pragma unroll
        for (int i = 0; i < 4; ++i) acc[mt][nt][i] = 0.f;

    __syncthreads();  // stage buffers free (prior half/phase reads done)
    load_tile(0, 0);
    const uint32_t aAddr0 = sAb + (wm * 64 + (lid & 15)) * 144 + (lid >> 4) * 16;
    const uint32_t bAddr0 = sAb + P1_B +
        (((lid >> 3) & 1) * 8 + (lid & 7)) * 272 + (wn * 32 + (lid >> 4) * 8) * 2;

#pragma unroll 1
    for (int it = 0; it < 8; ++it) {
      CP_WAIT(0);
      __syncthreads();
      if (it + 1 < 8) load_tile((it + 1) & 1, it + 1);
      const uint32_t sOA = (uint32_t)(it & 1) * 18432;
      const uint32_t sOB = (uint32_t)(it & 1) * 17408;
#pragma unroll
      for (int ks = 0; ks < 4; ++ks) {
        uint32_t afr[4][4];
        uint32_t bfr[4][2];
#pragma unroll
        for (int mt = 0; mt < 4; ++mt)
          ldsm_x4(afr[mt], aAddr0 + sOA + mt * 16 * 144 + ks * 32);
#pragma unroll
        for (int nt2 = 0; nt2 < 2; ++nt2) {
          uint32_t r4[4];
          ldsm_x4_t(r4, bAddr0 + sOB + ks * 16 * 272 + nt2 * 32);
          bfr[nt2 * 2 + 0][0] = r4[0]; bfr[nt2 * 2 + 0][1] = r4[1];
          bfr[nt2 * 2 + 1][0] = r4[2]; bfr[nt2 * 2 + 1][1] = r4[3];
        }
#pragma unroll
        for (int mt = 0; mt < 4; ++mt)
#pragma unroll
          for (int nt = 0; nt < 4; ++nt)
            mma_16816(acc[mt][nt], afr[mt], bfr[nt][0], bfr[nt][1]);
      }
    }
    __syncthreads();  // ALL B-stage reads done (hr-high writes may alias them)

    // 1/rowsum for the 128 rows of this half (A-stage region reuse)
    float* invb = (float*)smem;
    if (t < 128) {
      const float4 s4 = *(const float4*)&g_rowsum[(size_t)(r0 + t) * 4];
      invb[t] = 1.f / (s4.x + s4.y + s4.z + s4.w);
    }
    __syncthreads();

    // store acc*inv -> hr[c][lp] bf16
#pragma unroll
    for (int mt = 0; mt < 4; ++mt) {
      const int lr = wm * 64 + mt * 16 + (lid >> 2);
      const int c = half * 128 + lr;
      const float iv1 = invb[lr];
      const float iv2 = invb[lr + 8];
#pragma unroll
      for (int nt = 0; nt < 4; ++nt) {
        const int lp = wn * 32 + nt * 8 + (lid & 3) * 2;
        *(uint32_t*)((char*)hrp + c * 272 + lp * 2) =
            pack_bf16(acc[mt][nt][0] * iv1, acc[mt][nt][1] * iv1);
        *(uint32_t*)((char*)hrp + (c + 8) * 272 + lp * 2) =
            pack_bf16(acc[mt][nt][2] * iv2, acc[mt][nt][3] * iv2);
      }
    }
  }
  __syncthreads();  // hr complete & visible; A-stage region free

  // ---------------- Phase 2: two 128-co2 halves of y ----------------
  const float rz = rzp[0];
  const uint32_t aAddr2 = sAb + (wm * 64 + (lid & 15)) * 144 + (lid >> 4) * 16;
  const uint32_t bAddr2 = sAb + HR +
      (((lid >> 3) & 1) * 8 + (lid & 7)) * 272 + (wn * 32 + (lid >> 4) * 8) * 2;

#pragma unroll 1
  for (int cb = 0; cb < 2; ++cb) {
    const char* Awt =
        (const char*)(g_wTt + (size_t)g * 65536 + (size_t)cb * 128 * 256);

    auto loadA2 = [&](int s, int it) {
#pragma unroll
      for (int i = 0; i < 4; ++i) {
        const int idx = t + i * 256;
        const int row = idx >> 3, ch = idx & 7;
        cp_async16(sAb + s * 18432 + row * 144 + ch * 16,
                   Awt + (size_t)row * 512 + it * 128 + ch * 16);
      }
      CP_COMMIT();
    };

    float acc[4][4][4];
#pragma unroll
    for (int mt = 0; mt < 4; ++mt)
#pragma unroll
      for (int nt = 0; nt < 4; ++nt)
#pragma unroll
        for (int i = 0; i < 4; ++i) acc[mt][nt][i] = 0.f;

    loadA2(0, 0);

#pragma unroll 1
    for (int it = 0; it < 4; ++it) {
      CP_WAIT(0);
      __syncthreads();
      if (it + 1 < 4) loadA2((it + 1) & 1, it + 1);
      const uint32_t sOA = (uint32_t)(it & 1) * 18432;
      const uint32_t bIt = (uint32_t)(it * 64) * 272;
#pragma unroll
      for (int ks = 0; ks < 4; ++ks) {
        uint32_t afr[4][4];
        uint32_t bfr[4][2];
#pragma unroll
        for (int mt = 0; mt < 4; ++mt)
          ldsm_x4(afr[mt], aAddr2 + sOA + mt * 16 * 144 + ks * 32);
#pragma unroll
        for (int nt2 = 0; nt2 < 2; ++nt2) {
          uint32_t r4[4];
          ldsm_x4_t(r4, bAddr2 + bIt + ks * 16 * 272 + nt2 * 32);
          bfr[nt2 * 2 + 0][0] = r4[0]; bfr[nt2 * 2 + 0][1] = r4[1];
          bfr[nt2 * 2 + 1][0] = r4[2]; bfr[nt2 * 2 + 1][1] = r4[3];
        }
#pragma unroll
        for (int mt = 0; mt < 4; ++mt)
#pragma unroll
          for (int nt = 0; nt < 4; ++nt)
            mma_16816(acc[mt][nt], afr[mt], bfr[nt][0], bfr[nt][1]);
      }
    }
    __syncthreads();  // A-stage reads done -> safe to reuse as sY

    // stage raw y (pre-bias) into sY[co 64][l 264] bf16
    __nv_bfloat16* sY = (__nv_bfloat16*)smem;
#pragma unroll
    for (int mt = 0; mt < 4; ++mt) {
      const int r1 = wm * 64 + mt * 16 + (lid >> 2);
      const int r2 = r1 + 8;
#pragma unroll
      for (int nt = 0; nt < 4; ++nt) {
        const int lp = wn * 32 + nt * 8 + (lid & 3) * 2;
        sY[(r1 >> 1) * 264 + 2 * lp + (r1 & 1)] = __float2bfloat16(acc[mt][nt][0]);
        sY[(r1 >> 1) * 264 + 2 * (lp + 1) + (r1 & 1)] = __float2bfloat16(acc[mt][nt][1]);
        sY[(r2 >> 1) * 264 + 2 * lp + (r2 & 1)] = __float2bfloat16(acc[mt][nt][2]);
        sY[(r2 >> 1) * 264 + 2 * (lp + 1) + (r2 & 1)] = __float2bfloat16(acc[mt][nt][3]);
      }
    }
    __syncthreads();

    // residual write: bias + relu + x + rz*y, coalesced fp32
    const int co_r = t >> 2;
    const int colb = (t & 3) * 4;
    const int cog = g * 128 + cb * 64 + co_r;
    const float bias = bT[cog];
    const size_t rowoff = ((size_t)b * 256 + cog) * 2048 + by * 256;
#pragma unroll
    for (int j = 0; j < 16; ++j) {
      const int col = colb + j * 16;
      const uint32_t* yp = (const uint32_t*)&sY[co_r * 264 + col];
      __nv_bfloat162 y0 = *(const __nv_bfloat162*)&yp[0];
      __nv_bfloat162 y1 = *(const __nv_bfloat162*)&yp[1];
      const float4 xv = *(const float4*)(x + rowoff + col);
      float4 o4;
      o4.x = xv.x + rz * fmaxf(__bfloat162float(y0.x) + bias, 0.f);
      o4.y = xv.y + rz * fmaxf(__bfloat162float(y0.y) + bias, 0.f);
      o4.z = xv.z + rz * fmaxf(__bfloat162float(y1.x) + bias, 0.f);
      o4.w = xv.w + rz * fmaxf(__bfloat162float(y1.y) + bias, 0.f);
      *(float4*)(out + rowoff + col) = o4;
    }
    __syncthreads();  // sY region reused as A-stage next cb
  }
}

// ---------------------------------------------------------------------------
extern "C" void kernel_launch(void* const* d_in, const int* in_sizes, int n_in,
                              void* d_out, int out_size) {
  (void)in_sizes; (void)n_in; (void)out_size;
  const float* x        = (const float*)d_in[0];
  const float* w1       = (const float*)d_in[1];
  const float* b1       = (const float*)d_in[2];
  const float* patterns = (const float*)d_in[3];
  const float* wT       = (const float*)d_in[4];
  const float* bT       = (const float*)d_in[5];
  const float* RZ       = (const float*)d_in[6];
  float* out            = (float*)d_out;

  cudaFuncSetAttribute(kgemm_scores,
                       cudaFuncAttributeMaxDynamicSharedMemorySize, 73728);
  cudaFuncSetAttribute(k45_fused,
                       cudaFuncAttributeMaxDynamicSharedMemorySize, 106496);

  kprep_all<<<608, 256>>>(w1, wT, patterns);
  k1_hmma<<<dim3(16, 2, 32), 256>>>(x, b1);
  kgemm_scores<<<dim3(4, 64), 256, 73728>>>();
  k45_fused<<<dim3(8, 32), 256, 106496>>>(x, bT, RZ, out);
}